// round 1
// baseline (speedup 1.0000x reference)
#include <cuda_runtime.h>
#include <cstdio>

// Problem constants (match reference)
#define E_CNT   800000
#define N_NODES 50000
#define N_NF    16
#define N_EF    8
#define FEAT    40      // 2*N_NF + N_EF
#define HID     300
#define MSGD    128
#define NGRAPH  64
#define NPRED   8

// ------------------------------------------------------------------
// Scratch (device globals; no allocations allowed in kernel_launch)
// ------------------------------------------------------------------
__device__ float g_feat[(size_t)E_CNT * FEAT];
__device__ float g_buf1[(size_t)E_CNT * HID];
__device__ float g_buf2[(size_t)E_CNT * HID];
__device__ float g_aggr[(size_t)N_NODES * MSGD];
__device__ float g_n1[(size_t)N_NODES * HID];
__device__ float g_n2[(size_t)N_NODES * HID];
__device__ float g_gsum[NGRAPH * HID];
__device__ float g_gcnt[NGRAPH];

// ------------------------------------------------------------------
// Fused gather: feat[e] = concat(x[dst[e]], x[src[e]], edge_attr[e])
// ------------------------------------------------------------------
__global__ void gather_feat_kernel(const float* __restrict__ x,
                                   const int* __restrict__ src,
                                   const int* __restrict__ dst,
                                   const float* __restrict__ ea,
                                   float* __restrict__ feat, int E)
{
    long long idx = (long long)blockIdx.x * blockDim.x + threadIdx.x;
    long long total = (long long)E * FEAT;
    if (idx >= total) return;
    int e = (int)(idx / FEAT);
    int f = (int)(idx % FEAT);
    float v;
    if (f < N_NF) {
        v = x[(size_t)dst[e] * N_NF + f];
    } else if (f < 2 * N_NF) {
        v = x[(size_t)src[e] * N_NF + (f - N_NF)];
    } else {
        v = ea[(size_t)e * N_EF + (f - 2 * N_NF)];
    }
    feat[idx] = v;
}

// ------------------------------------------------------------------
// Tiled GEMM:  C[M,N] = act(A[M,K] @ W[K,N] + bias)
// BM=128, BN=64, BK=16, 256 threads, 8x4 register tile per thread.
// ------------------------------------------------------------------
#define BM 128
#define BN 64
#define BKK 16
#define TM 8
#define TN 4

__global__ __launch_bounds__(256)
void gemm_bias_act(const float* __restrict__ A,
                   const float* __restrict__ W,
                   const float* __restrict__ bias,
                   float* __restrict__ C,
                   int M, int K, int N, int do_relu)
{
    __shared__ float As[BKK][BM];
    __shared__ float Ws[BKK][BN + 4];   // pad to ease bank conflicts

    const int tid = threadIdx.x;
    const int m0 = blockIdx.x * BM;
    const int n0 = blockIdx.y * BN;

    const int rm = (tid >> 4) * TM;  // 0..120
    const int rn = (tid & 15) * TN;  // 0..60

    float acc[TM][TN];
#pragma unroll
    for (int i = 0; i < TM; i++)
#pragma unroll
        for (int j = 0; j < TN; j++) acc[i][j] = 0.f;

    for (int k0 = 0; k0 < K; k0 += BKK) {
        // Load A tile: BM*BKK = 2048 elems, 8 per thread.
#pragma unroll
        for (int i = 0; i < 8; i++) {
            int idx = tid + i * 256;
            int kk = idx & 15;
            int mm = idx >> 4;
            int m = m0 + mm, k = k0 + kk;
            As[kk][mm] = (m < M && k < K) ? A[(size_t)m * K + k] : 0.f;
        }
        // Load W tile: BKK*BN = 1024 elems, 4 per thread.
#pragma unroll
        for (int i = 0; i < 4; i++) {
            int idx = tid + i * 256;
            int nn = idx & 63;
            int kk = idx >> 6;
            int k = k0 + kk, n = n0 + nn;
            Ws[kk][nn] = (k < K && n < N) ? W[(size_t)k * N + n] : 0.f;
        }
        __syncthreads();

#pragma unroll
        for (int kk = 0; kk < BKK; kk++) {
            float a[TM], w[TN];
#pragma unroll
            for (int i = 0; i < TM; i++) a[i] = As[kk][rm + i];
#pragma unroll
            for (int j = 0; j < TN; j++) w[j] = Ws[kk][rn + j];
#pragma unroll
            for (int i = 0; i < TM; i++)
#pragma unroll
                for (int j = 0; j < TN; j++)
                    acc[i][j] = fmaf(a[i], w[j], acc[i][j]);
        }
        __syncthreads();
    }

#pragma unroll
    for (int i = 0; i < TM; i++) {
        int m = m0 + rm + i;
        if (m >= M) continue;
#pragma unroll
        for (int j = 0; j < TN; j++) {
            int n = n0 + rn + j;
            if (n >= N) continue;
            float v = acc[i][j] + bias[n];
            if (do_relu) v = fmaxf(v, 0.f);
            C[(size_t)m * N + n] = v;
        }
    }
}

// ------------------------------------------------------------------
// Scatter-add messages into target nodes: aggr[dst[e]] += msg[e]
// One thread handles 4 consecutive features of one edge (float4 read).
// ------------------------------------------------------------------
__global__ void scatter_msg_kernel(const float* __restrict__ msg,
                                   const int* __restrict__ dst,
                                   float* __restrict__ aggr, int E)
{
    long long idx = (long long)blockIdx.x * blockDim.x + threadIdx.x;
    long long total = (long long)E * (MSGD / 4);
    if (idx >= total) return;
    int e = (int)(idx / (MSGD / 4));
    int j4 = (int)(idx % (MSGD / 4));
    const float4 v = reinterpret_cast<const float4*>(msg)[(size_t)e * (MSGD / 4) + j4];
    float* base = aggr + (size_t)dst[e] * MSGD + j4 * 4;
    atomicAdd(base + 0, v.x);
    atomicAdd(base + 1, v.y);
    atomicAdd(base + 2, v.z);
    atomicAdd(base + 3, v.w);
}

// ------------------------------------------------------------------
// Global pooling: gsum[batch[n]] += node[n]; gcnt[batch[n]] += 1
// ------------------------------------------------------------------
__global__ void pool_sum_kernel(const float* __restrict__ node,
                                const int* __restrict__ batch,
                                float* __restrict__ gsum, int Nn)
{
    long long idx = (long long)blockIdx.x * blockDim.x + threadIdx.x;
    long long total = (long long)Nn * HID;
    if (idx >= total) return;
    int n = (int)(idx / HID);
    int f = (int)(idx % HID);
    atomicAdd(&gsum[batch[n] * HID + f], node[idx]);
}

__global__ void pool_cnt_kernel(const int* __restrict__ batch,
                                float* __restrict__ gcnt, int Nn)
{
    int n = blockIdx.x * blockDim.x + threadIdx.x;
    if (n >= Nn) return;
    atomicAdd(&gcnt[batch[n]], 1.0f);
}

// ------------------------------------------------------------------
// Final: out[g,p] = (gsum[g]/max(cnt,1)) @ lw + lb     (64 x 8)
// ------------------------------------------------------------------
__global__ void final_kernel(const float* __restrict__ gsum,
                             const float* __restrict__ gcnt,
                             const float* __restrict__ lw,
                             const float* __restrict__ lb,
                             float* __restrict__ out)
{
    int t = threadIdx.x;              // 512 threads
    if (t >= NGRAPH * NPRED) return;
    int g = t / NPRED;
    int p = t % NPRED;
    float inv = 1.0f / fmaxf(gcnt[g], 1.0f);
    float s = 0.f;
    for (int k = 0; k < HID; k++)
        s = fmaf(gsum[g * HID + k] * inv, lw[k * NPRED + p], s);
    out[t] = s + lb[p];
}

// ------------------------------------------------------------------
// Launch
// ------------------------------------------------------------------
static inline int cdiv(int a, int b) { return (a + b - 1) / b; }

extern "C" void kernel_launch(void* const* d_in, const int* in_sizes, int n_in,
                              void* d_out, int out_size)
{
    const float* x   = (const float*)d_in[0];
    const int*   ei  = (const int*)d_in[1];
    const float* ea  = (const float*)d_in[2];
    const int*   bat = (const int*)d_in[3];
    const float* mw1 = (const float*)d_in[4];
    const float* mb1 = (const float*)d_in[5];
    const float* mw2 = (const float*)d_in[6];
    const float* mb2 = (const float*)d_in[7];
    const float* mw3 = (const float*)d_in[8];
    const float* mb3 = (const float*)d_in[9];
    const float* mw4 = (const float*)d_in[10];
    const float* mb4 = (const float*)d_in[11];
    const float* nw1 = (const float*)d_in[12];
    const float* nb1 = (const float*)d_in[13];
    const float* nw2 = (const float*)d_in[14];
    const float* nb2 = (const float*)d_in[15];
    const float* nw3 = (const float*)d_in[16];
    const float* nb3 = (const float*)d_in[17];
    const float* nw4 = (const float*)d_in[18];
    const float* nb4 = (const float*)d_in[19];
    const float* lw  = (const float*)d_in[20];
    const float* lb  = (const float*)d_in[21];
    float* out = (float*)d_out;

    const int E  = in_sizes[1] / 2;       // edge_index is [2, E]
    const int Nn = in_sizes[0] / N_NF;    // x is [N, 16]
    const int* src = ei;                  // row 0
    const int* dst = ei + E;              // row 1

    float *feat, *buf1, *buf2, *aggr, *n1, *n2, *gsum, *gcnt;
    cudaGetSymbolAddress((void**)&feat, g_feat);
    cudaGetSymbolAddress((void**)&buf1, g_buf1);
    cudaGetSymbolAddress((void**)&buf2, g_buf2);
    cudaGetSymbolAddress((void**)&aggr, g_aggr);
    cudaGetSymbolAddress((void**)&n1,   g_n1);
    cudaGetSymbolAddress((void**)&n2,   g_n2);
    cudaGetSymbolAddress((void**)&gsum, g_gsum);
    cudaGetSymbolAddress((void**)&gcnt, g_gcnt);

    // Zero accumulation buffers (async memsets are graph-capturable)
    cudaMemsetAsync(aggr, 0, (size_t)N_NODES * MSGD * sizeof(float));
    cudaMemsetAsync(gsum, 0, (size_t)NGRAPH * HID * sizeof(float));
    cudaMemsetAsync(gcnt, 0, (size_t)NGRAPH * sizeof(float));

    // 1. Gather edge features [E, 40]
    {
        long long total = (long long)E * FEAT;
        gather_feat_kernel<<<(int)((total + 255) / 256), 256>>>(x, src, dst, ea, feat, E);
    }

    // 2. Edge (message) MLP: 40->300->300->300->128
    {
        dim3 grid;
        grid = dim3(cdiv(E, BM), cdiv(HID, BN));
        gemm_bias_act<<<grid, 256>>>(feat, mw1, mb1, buf1, E, FEAT, HID, 1);
        gemm_bias_act<<<grid, 256>>>(buf1, mw2, mb2, buf2, E, HID, HID, 1);
        gemm_bias_act<<<grid, 256>>>(buf2, mw3, mb3, buf1, E, HID, HID, 1);
        grid = dim3(cdiv(E, BM), cdiv(MSGD, BN));
        gemm_bias_act<<<grid, 256>>>(buf1, mw4, mb4, buf2, E, HID, MSGD, 0);
    }

    // 3. Scatter-add into nodes
    {
        long long total = (long long)E * (MSGD / 4);
        scatter_msg_kernel<<<(int)((total + 255) / 256), 256>>>(buf2, dst, aggr, E);
    }

    // 4. Node MLP: 128->300->300->300->300
    {
        dim3 grid(cdiv(Nn, BM), cdiv(HID, BN));
        gemm_bias_act<<<grid, 256>>>(aggr, nw1, nb1, n1, Nn, MSGD, HID, 1);
        gemm_bias_act<<<grid, 256>>>(n1,   nw2, nb2, n2, Nn, HID,  HID, 1);
        gemm_bias_act<<<grid, 256>>>(n2,   nw3, nb3, n1, Nn, HID,  HID, 1);
        gemm_bias_act<<<grid, 256>>>(n1,   nw4, nb4, n2, Nn, HID,  HID, 0);
    }

    // 5. Global mean pool
    {
        long long total = (long long)Nn * HID;
        pool_sum_kernel<<<(int)((total + 255) / 256), 256>>>(n2, bat, gsum, Nn);
        pool_cnt_kernel<<<cdiv(Nn, 256), 256>>>(bat, gcnt, Nn);
    }

    // 6. pooled @ lw + lb -> out [64, 8]
    final_kernel<<<1, 512>>>(gsum, gcnt, lw, lb, out);
}

// round 2
// speedup vs baseline: 1.6969x; 1.6969x over previous
#include <cuda_runtime.h>
#include <cstdint>

// Problem constants (match reference)
#define E_CNT   800000
#define N_NODES 50000
#define N_NF    16
#define N_EF    8
#define FEAT    40      // 2*N_NF + N_EF
#define HID     300
#define MSGD    128
#define NGRAPH  64
#define NPRED   8

// ------------------------------------------------------------------
// Scratch (device globals; no allocations allowed in kernel_launch)
// ------------------------------------------------------------------
__device__ float g_feat[(size_t)E_CNT * FEAT];
__device__ float g_buf1[(size_t)E_CNT * HID];
__device__ float g_buf2[(size_t)E_CNT * HID];
__device__ float g_aggr[(size_t)N_NODES * MSGD];
__device__ float g_n1[(size_t)N_NODES * HID];
__device__ float g_n2[(size_t)N_NODES * HID];
__device__ float g_gsum[NGRAPH * HID];
__device__ float g_gcnt[NGRAPH];

// ------------------------------------------------------------------
// Fused gather: feat[e] = concat(x[dst[e]], x[src[e]], edge_attr[e])
// ------------------------------------------------------------------
__global__ void gather_feat_kernel(const float* __restrict__ x,
                                   const int* __restrict__ src,
                                   const int* __restrict__ dst,
                                   const float* __restrict__ ea,
                                   float* __restrict__ feat, int E)
{
    long long idx = (long long)blockIdx.x * blockDim.x + threadIdx.x;
    long long total = (long long)E * FEAT;
    if (idx >= total) return;
    int e = (int)(idx / FEAT);
    int f = (int)(idx % FEAT);
    float v;
    if (f < N_NF) {
        v = x[(size_t)dst[e] * N_NF + f];
    } else if (f < 2 * N_NF) {
        v = x[(size_t)src[e] * N_NF + (f - N_NF)];
    } else {
        v = ea[(size_t)e * N_EF + (f - 2 * N_NF)];
    }
    feat[idx] = v;
}

// ------------------------------------------------------------------
// tf32 tensor-core GEMM: C[M,N] = act(A[M,K] @ W[K,N] + bias)
// BM=128, BN=64, BK=32; 8 warps in 4(M)x2(N); warp tile 32x32
// via 2x4 mma.sync.m16n8k8.tf32 fragments.
// ------------------------------------------------------------------
#define BM 128
#define BN 64
#define BK 32

__device__ __forceinline__ uint32_t f2tf32(float v) {
    uint32_t t;
    asm("cvt.rna.tf32.f32 %0, %1;" : "=r"(t) : "f"(v));
    return t;
}

__global__ __launch_bounds__(256)
void gemm_tf32(const float* __restrict__ A,
               const float* __restrict__ W,
               const float* __restrict__ bias,
               float* __restrict__ C,
               int M, int K, int N, int do_relu)
{
    __shared__ uint32_t As[BM][BK + 4];   // bank-bijective for A frag loads
    __shared__ uint32_t Ws[BK][BN + 8];   // bank-bijective for B frag loads

    const int tid  = threadIdx.x;
    const int warp = tid >> 5;
    const int lane = tid & 31;
    const int wm = (warp & 3) * 32;   // warp M offset within block tile
    const int wn = (warp >> 2) * 32;  // warp N offset
    const int m0 = blockIdx.x * BM;
    const int n0 = blockIdx.y * BN;

    const int lr = lane >> 2;  // 0..7
    const int lc = lane & 3;   // 0..3

    float acc[2][4][4];
#pragma unroll
    for (int mi = 0; mi < 2; mi++)
#pragma unroll
        for (int ni = 0; ni < 4; ni++)
#pragma unroll
            for (int r = 0; r < 4; r++) acc[mi][ni][r] = 0.f;

    for (int k0 = 0; k0 < K; k0 += BK) {
        // Load A tile: BM*BK = 4096 elems, 16/thread, coalesced over k.
#pragma unroll
        for (int i = 0; i < 16; i++) {
            int idx = tid + i * 256;
            int mm = idx >> 5, kk = idx & 31;
            int m = m0 + mm, k = k0 + kk;
            float v = (m < M && k < K) ? A[(size_t)m * K + k] : 0.f;
            As[mm][kk] = f2tf32(v);
        }
        // Load W tile: BK*BN = 2048 elems, 8/thread, coalesced over n.
#pragma unroll
        for (int i = 0; i < 8; i++) {
            int idx = tid + i * 256;
            int kk = idx >> 6, nn = idx & 63;
            int k = k0 + kk, n = n0 + nn;
            float v = (k < K && n < N) ? W[(size_t)k * N + n] : 0.f;
            Ws[kk][nn] = f2tf32(v);
        }
        __syncthreads();

#pragma unroll
        for (int ks = 0; ks < BK; ks += 8) {
            uint32_t a[2][4], b[4][2];
#pragma unroll
            for (int mi = 0; mi < 2; mi++) {
                int mb = wm + mi * 16;
                a[mi][0] = As[mb + lr    ][ks + lc    ];
                a[mi][1] = As[mb + lr + 8][ks + lc    ];
                a[mi][2] = As[mb + lr    ][ks + lc + 4];
                a[mi][3] = As[mb + lr + 8][ks + lc + 4];
            }
#pragma unroll
            for (int ni = 0; ni < 4; ni++) {
                int nb = wn + ni * 8;
                b[ni][0] = Ws[ks + lc    ][nb + lr];
                b[ni][1] = Ws[ks + lc + 4][nb + lr];
            }
#pragma unroll
            for (int mi = 0; mi < 2; mi++)
#pragma unroll
                for (int ni = 0; ni < 4; ni++) {
                    asm volatile(
                        "mma.sync.aligned.m16n8k8.row.col.f32.tf32.tf32.f32 "
                        "{%0,%1,%2,%3}, {%4,%5,%6,%7}, {%8,%9}, {%0,%1,%2,%3};\n"
                        : "+f"(acc[mi][ni][0]), "+f"(acc[mi][ni][1]),
                          "+f"(acc[mi][ni][2]), "+f"(acc[mi][ni][3])
                        : "r"(a[mi][0]), "r"(a[mi][1]), "r"(a[mi][2]), "r"(a[mi][3]),
                          "r"(b[ni][0]), "r"(b[ni][1]));
                }
        }
        __syncthreads();
    }

    // Epilogue: bias + optional ReLU, direct global store.
#pragma unroll
    for (int mi = 0; mi < 2; mi++) {
#pragma unroll
        for (int ni = 0; ni < 4; ni++) {
            int row0 = m0 + wm + mi * 16 + lr;
            int col  = n0 + wn + ni * 8 + lc * 2;
#pragma unroll
            for (int half = 0; half < 2; half++) {
                int row = row0 + half * 8;
                if (row < M) {
                    if (col < N) {
                        float v = acc[mi][ni][half * 2 + 0] + bias[col];
                        if (do_relu) v = fmaxf(v, 0.f);
                        C[(size_t)row * N + col] = v;
                    }
                    if (col + 1 < N) {
                        float v = acc[mi][ni][half * 2 + 1] + bias[col + 1];
                        if (do_relu) v = fmaxf(v, 0.f);
                        C[(size_t)row * N + col + 1] = v;
                    }
                }
            }
        }
    }
}

// ------------------------------------------------------------------
// Scatter-add messages into target nodes: aggr[dst[e]] += msg[e]
// ------------------------------------------------------------------
__global__ void scatter_msg_kernel(const float* __restrict__ msg,
                                   const int* __restrict__ dst,
                                   float* __restrict__ aggr, int E)
{
    long long idx = (long long)blockIdx.x * blockDim.x + threadIdx.x;
    long long total = (long long)E * (MSGD / 4);
    if (idx >= total) return;
    int e = (int)(idx / (MSGD / 4));
    int j4 = (int)(idx % (MSGD / 4));
    const float4 v = reinterpret_cast<const float4*>(msg)[(size_t)e * (MSGD / 4) + j4];
    float* base = aggr + (size_t)dst[e] * MSGD + j4 * 4;
    atomicAdd(base + 0, v.x);
    atomicAdd(base + 1, v.y);
    atomicAdd(base + 2, v.z);
    atomicAdd(base + 3, v.w);
}

// ------------------------------------------------------------------
// Global pooling: gsum[batch[n]] += node[n]; gcnt[batch[n]] += 1
// ------------------------------------------------------------------
__global__ void pool_sum_kernel(const float* __restrict__ node,
                                const int* __restrict__ batch,
                                float* __restrict__ gsum, int Nn)
{
    long long idx = (long long)blockIdx.x * blockDim.x + threadIdx.x;
    long long total = (long long)Nn * HID;
    if (idx >= total) return;
    int n = (int)(idx / HID);
    int f = (int)(idx % HID);
    atomicAdd(&gsum[batch[n] * HID + f], node[idx]);
}

__global__ void pool_cnt_kernel(const int* __restrict__ batch,
                                float* __restrict__ gcnt, int Nn)
{
    int n = blockIdx.x * blockDim.x + threadIdx.x;
    if (n >= Nn) return;
    atomicAdd(&gcnt[batch[n]], 1.0f);
}

// ------------------------------------------------------------------
// Final: out[g,p] = (gsum[g]/max(cnt,1)) @ lw + lb     (64 x 8)
// ------------------------------------------------------------------
__global__ void final_kernel(const float* __restrict__ gsum,
                             const float* __restrict__ gcnt,
                             const float* __restrict__ lw,
                             const float* __restrict__ lb,
                             float* __restrict__ out)
{
    int t = threadIdx.x;              // 512 threads
    if (t >= NGRAPH * NPRED) return;
    int g = t / NPRED;
    int p = t % NPRED;
    float inv = 1.0f / fmaxf(gcnt[g], 1.0f);
    float s = 0.f;
    for (int k = 0; k < HID; k++)
        s = fmaf(gsum[g * HID + k] * inv, lw[k * NPRED + p], s);
    out[t] = s + lb[p];
}

// ------------------------------------------------------------------
// Launch
// ------------------------------------------------------------------
static inline int cdiv(int a, int b) { return (a + b - 1) / b; }

extern "C" void kernel_launch(void* const* d_in, const int* in_sizes, int n_in,
                              void* d_out, int out_size)
{
    const float* x   = (const float*)d_in[0];
    const int*   ei  = (const int*)d_in[1];
    const float* ea  = (const float*)d_in[2];
    const int*   bat = (const int*)d_in[3];
    const float* mw1 = (const float*)d_in[4];
    const float* mb1 = (const float*)d_in[5];
    const float* mw2 = (const float*)d_in[6];
    const float* mb2 = (const float*)d_in[7];
    const float* mw3 = (const float*)d_in[8];
    const float* mb3 = (const float*)d_in[9];
    const float* mw4 = (const float*)d_in[10];
    const float* mb4 = (const float*)d_in[11];
    const float* nw1 = (const float*)d_in[12];
    const float* nb1 = (const float*)d_in[13];
    const float* nw2 = (const float*)d_in[14];
    const float* nb2 = (const float*)d_in[15];
    const float* nw3 = (const float*)d_in[16];
    const float* nb3 = (const float*)d_in[17];
    const float* nw4 = (const float*)d_in[18];
    const float* nb4 = (const float*)d_in[19];
    const float* lw  = (const float*)d_in[20];
    const float* lb  = (const float*)d_in[21];
    float* out = (float*)d_out;

    const int E  = in_sizes[1] / 2;       // edge_index is [2, E]
    const int Nn = in_sizes[0] / N_NF;    // x is [N, 16]
    const int* src = ei;                  // row 0
    const int* dst = ei + E;              // row 1

    float *feat, *buf1, *buf2, *aggr, *n1, *n2, *gsum, *gcnt;
    cudaGetSymbolAddress((void**)&feat, g_feat);
    cudaGetSymbolAddress((void**)&buf1, g_buf1);
    cudaGetSymbolAddress((void**)&buf2, g_buf2);
    cudaGetSymbolAddress((void**)&aggr, g_aggr);
    cudaGetSymbolAddress((void**)&n1,   g_n1);
    cudaGetSymbolAddress((void**)&n2,   g_n2);
    cudaGetSymbolAddress((void**)&gsum, g_gsum);
    cudaGetSymbolAddress((void**)&gcnt, g_gcnt);

    cudaMemsetAsync(aggr, 0, (size_t)N_NODES * MSGD * sizeof(float));
    cudaMemsetAsync(gsum, 0, (size_t)NGRAPH * HID * sizeof(float));
    cudaMemsetAsync(gcnt, 0, (size_t)NGRAPH * sizeof(float));

    // 1. Gather edge features [E, 40]
    {
        long long total = (long long)E * FEAT;
        gather_feat_kernel<<<(int)((total + 255) / 256), 256>>>(x, src, dst, ea, feat, E);
    }

    // 2. Edge (message) MLP: 40->300->300->300->128
    {
        dim3 grid;
        grid = dim3(cdiv(E, BM), cdiv(HID, BN));
        gemm_tf32<<<grid, 256>>>(feat, mw1, mb1, buf1, E, FEAT, HID, 1);
        gemm_tf32<<<grid, 256>>>(buf1, mw2, mb2, buf2, E, HID, HID, 1);
        gemm_tf32<<<grid, 256>>>(buf2, mw3, mb3, buf1, E, HID, HID, 1);
        grid = dim3(cdiv(E, BM), cdiv(MSGD, BN));
        gemm_tf32<<<grid, 256>>>(buf1, mw4, mb4, buf2, E, HID, MSGD, 0);
    }

    // 3. Scatter-add into nodes
    {
        long long total = (long long)E * (MSGD / 4);
        scatter_msg_kernel<<<(int)((total + 255) / 256), 256>>>(buf2, dst, aggr, E);
    }

    // 4. Node MLP: 128->300->300->300->300
    {
        dim3 grid(cdiv(Nn, BM), cdiv(HID, BN));
        gemm_tf32<<<grid, 256>>>(aggr, nw1, nb1, n1, Nn, MSGD, HID, 1);
        gemm_tf32<<<grid, 256>>>(n1,   nw2, nb2, n2, Nn, HID,  HID, 1);
        gemm_tf32<<<grid, 256>>>(n2,   nw3, nb3, n1, Nn, HID,  HID, 1);
        gemm_tf32<<<grid, 256>>>(n1,   nw4, nb4, n2, Nn, HID,  HID, 0);
    }

    // 5. Global mean pool
    {
        long long total = (long long)Nn * HID;
        pool_sum_kernel<<<(int)((total + 255) / 256), 256>>>(n2, bat, gsum, Nn);
        pool_cnt_kernel<<<cdiv(Nn, 256), 256>>>(bat, gcnt, Nn);
    }

    // 6. pooled @ lw + lb -> out [64, 8]
    final_kernel<<<1, 512>>>(gsum, gcnt, lw, lb, out);
}

// round 4
// speedup vs baseline: 3.9483x; 2.3267x over previous
#include <cuda_runtime.h>
#include <cstdint>

// Problem constants (match reference)
#define E_CNT   800000
#define N_NODES 50000
#define N_NF    16
#define N_EF    8
#define FEAT    40      // 2*N_NF + N_EF
#define HID     300
#define MSGD    128
#define NGRAPH  64
#define NPRED   8

// ------------------------------------------------------------------
// Scratch (device globals)
// ------------------------------------------------------------------
__device__ float g_feat[(size_t)E_CNT * FEAT];
__device__ float g_buf1[(size_t)E_CNT * HID];
__device__ float g_buf2[(size_t)E_CNT * HID];
__device__ float g_aggr[(size_t)N_NODES * MSGD];
__device__ float g_n1[(size_t)N_NODES * HID];
__device__ float g_n2[(size_t)N_NODES * HID];
__device__ float g_gsum[NGRAPH * HID];
__device__ float g_gcnt[NGRAPH];

// ------------------------------------------------------------------
// Fused gather: feat[e] = concat(x[dst[e]], x[src[e]], edge_attr[e])
// ------------------------------------------------------------------
__global__ void gather_feat_kernel(const float* __restrict__ x,
                                   const int* __restrict__ src,
                                   const int* __restrict__ dst,
                                   const float* __restrict__ ea,
                                   float* __restrict__ feat, int E)
{
    long long idx = (long long)blockIdx.x * blockDim.x + threadIdx.x;
    long long total = (long long)E * FEAT;
    if (idx >= total) return;
    int e = (int)(idx / FEAT);
    int f = (int)(idx % FEAT);
    float v;
    if (f < N_NF) {
        v = x[(size_t)dst[e] * N_NF + f];
    } else if (f < 2 * N_NF) {
        v = x[(size_t)src[e] * N_NF + (f - N_NF)];
    } else {
        v = ea[(size_t)e * N_EF + (f - 2 * N_NF)];
    }
    feat[idx] = v;
}

// ------------------------------------------------------------------
// tf32 tensor-core GEMM with cp.async double buffering.
// C[M,N] = act(A[M,K] @ W[K,N] + bias), optionally scatter-added:
//   idx == nullptr : C[m,n] = v
//   idx != nullptr : atomicAdd(&C[idx[m]*N + n], v)
// Grid: x = N-tile (varies fastest -> A tiles shared in L2), y = M-tile.
// BM=128, BN=64, BK=32; 8 warps 4(M)x2(N); warp tile 32x32 via
// 2x4 mma.sync.m16n8k8.tf32. cvt.rna.tf32 applied at fragment load
// (round-to-nearest; raw truncation fails the 1e-3 tolerance).
// ------------------------------------------------------------------
#define BM 128
#define BN 64
#define BK 32

__device__ __forceinline__ void cp_async16(float* sptr, const float* gptr, bool pred)
{
    uint32_t saddr = (uint32_t)__cvta_generic_to_shared(sptr);
    int sz = pred ? 16 : 0;
    asm volatile("cp.async.cg.shared.global [%0], [%1], 16, %2;\n"
                 :: "r"(saddr), "l"(gptr), "r"(sz));
}
__device__ __forceinline__ void cp_async_commit() {
    asm volatile("cp.async.commit_group;\n" ::: "memory");
}
template<int N_> __device__ __forceinline__ void cp_async_wait() {
    asm volatile("cp.async.wait_group %0;\n" :: "n"(N_) : "memory");
}
__device__ __forceinline__ uint32_t f2tf32(float v) {
    uint32_t t;
    asm("cvt.rna.tf32.f32 %0, %1;" : "=r"(t) : "f"(v));
    return t;
}

__global__ __launch_bounds__(256)
void gemm_tf32(const float* __restrict__ A,
               const float* __restrict__ W,
               const float* __restrict__ bias,
               float* __restrict__ C,
               const int* __restrict__ idx,
               int M, int K, int N, int do_relu)
{
    __shared__ float As[2][BM][BK + 4];   // row stride 36 -> conflict-free frags
    __shared__ float Ws[2][BK][BN + 8];   // row stride 72 -> conflict-free frags

    const int tid  = threadIdx.x;
    const int warp = tid >> 5;
    const int lane = tid & 31;
    const int wm = (warp & 3) * 32;
    const int wn = (warp >> 2) * 32;
    const int n0 = blockIdx.x * BN;   // N-tile fastest => A reuse in L2
    const int m0 = blockIdx.y * BM;

    const int lr = lane >> 2;  // 0..7
    const int lc = lane & 3;   // 0..3

    // Per-thread cp.async chunk coordinates (A: 4 chunks, W: 2 chunks)
    int mmA[4], kcA[4];
    const float* agp[4];
    bool rowOkA[4];
#pragma unroll
    for (int i = 0; i < 4; i++) {
        int c = tid + i * 256;
        mmA[i] = c >> 3;           // 8 chunks per 32-float row
        kcA[i] = (c & 7) * 4;
        rowOkA[i] = (m0 + mmA[i]) < M;
        agp[i] = A + (size_t)(rowOkA[i] ? (m0 + mmA[i]) : 0) * K + kcA[i];
    }
    int kkW[2], ncW[2];
    const float* wgp[2];
    bool colOkW[2];
#pragma unroll
    for (int i = 0; i < 2; i++) {
        int c = tid + i * 256;
        kkW[i] = c >> 4;           // 16 chunks per 64-float row
        ncW[i] = (c & 15) * 4;
        colOkW[i] = (n0 + ncW[i]) < N;
        wgp[i] = W + (size_t)kkW[i] * N + n0 + ncW[i];
    }

    float acc[2][4][4];
#pragma unroll
    for (int mi = 0; mi < 2; mi++)
#pragma unroll
        for (int ni = 0; ni < 4; ni++)
#pragma unroll
            for (int r = 0; r < 4; r++) acc[mi][ni][r] = 0.f;

    const int nsteps = (K + BK - 1) / BK;

    // Prologue: load stage 0 into buffer 0
    {
#pragma unroll
        for (int i = 0; i < 4; i++)
            cp_async16(&As[0][mmA[i]][kcA[i]], agp[i], rowOkA[i] && (kcA[i] < K));
#pragma unroll
        for (int i = 0; i < 2; i++)
            cp_async16(&Ws[0][kkW[i]][ncW[i]], wgp[i], colOkW[i] && (kkW[i] < K));
        cp_async_commit();
    }

    for (int s = 0; s < nsteps; s++) {
        const int buf = s & 1;
        if (s + 1 < nsteps) {
            const int k0n = (s + 1) * BK;
            const int nb = buf ^ 1;
#pragma unroll
            for (int i = 0; i < 4; i++)
                cp_async16(&As[nb][mmA[i]][kcA[i]], agp[i] + k0n,
                           rowOkA[i] && (k0n + kcA[i] < K));
#pragma unroll
            for (int i = 0; i < 2; i++)
                cp_async16(&Ws[nb][kkW[i]][ncW[i]], wgp[i] + (size_t)k0n * N,
                           colOkW[i] && (k0n + kkW[i] < K));
            cp_async_commit();
            cp_async_wait<1>();
        } else {
            cp_async_wait<0>();
        }
        __syncthreads();

#pragma unroll
        for (int ks = 0; ks < BK; ks += 8) {
            uint32_t a[2][4], b[4][2];
#pragma unroll
            for (int mi = 0; mi < 2; mi++) {
                int mb = wm + mi * 16;
                a[mi][0] = f2tf32(As[buf][mb + lr    ][ks + lc    ]);
                a[mi][1] = f2tf32(As[buf][mb + lr + 8][ks + lc    ]);
                a[mi][2] = f2tf32(As[buf][mb + lr    ][ks + lc + 4]);
                a[mi][3] = f2tf32(As[buf][mb + lr + 8][ks + lc + 4]);
            }
#pragma unroll
            for (int ni = 0; ni < 4; ni++) {
                int nb = wn + ni * 8;
                b[ni][0] = f2tf32(Ws[buf][ks + lc    ][nb + lr]);
                b[ni][1] = f2tf32(Ws[buf][ks + lc + 4][nb + lr]);
            }
#pragma unroll
            for (int mi = 0; mi < 2; mi++)
#pragma unroll
                for (int ni = 0; ni < 4; ni++) {
                    asm volatile(
                        "mma.sync.aligned.m16n8k8.row.col.f32.tf32.tf32.f32 "
                        "{%0,%1,%2,%3}, {%4,%5,%6,%7}, {%8,%9}, {%0,%1,%2,%3};\n"
                        : "+f"(acc[mi][ni][0]), "+f"(acc[mi][ni][1]),
                          "+f"(acc[mi][ni][2]), "+f"(acc[mi][ni][3])
                        : "r"(a[mi][0]), "r"(a[mi][1]), "r"(a[mi][2]), "r"(a[mi][3]),
                          "r"(b[ni][0]), "r"(b[ni][1]));
                }
        }
        __syncthreads();  // protect buf before next iteration's cp.async reuses it
    }

    // Epilogue: bias (+ReLU) then store or scatter-atomicAdd.
#pragma unroll
    for (int mi = 0; mi < 2; mi++) {
#pragma unroll
        for (int half = 0; half < 2; half++) {
            int row = m0 + wm + mi * 16 + lr + half * 8;
            if (row >= M) continue;
            long long obase;
            if (idx) obase = (long long)idx[row] * N;
            else     obase = (long long)row * N;
#pragma unroll
            for (int ni = 0; ni < 4; ni++) {
                int col = n0 + wn + ni * 8 + lc * 2;
                float v0 = acc[mi][ni][half * 2 + 0];
                float v1 = acc[mi][ni][half * 2 + 1];
                if (col < N) {
                    float v = v0 + bias[col];
                    if (do_relu) v = fmaxf(v, 0.f);
                    if (idx) atomicAdd(&C[obase + col], v);
                    else     C[obase + col] = v;
                }
                if (col + 1 < N) {
                    float v = v1 + bias[col + 1];
                    if (do_relu) v = fmaxf(v, 0.f);
                    if (idx) atomicAdd(&C[obase + col + 1], v);
                    else     C[obase + col + 1] = v;
                }
            }
        }
    }
}

// ------------------------------------------------------------------
// Pool count: gcnt[batch[n]] += 1
// ------------------------------------------------------------------
__global__ void pool_cnt_kernel(const int* __restrict__ batch,
                                float* __restrict__ gcnt, int Nn)
{
    int n = blockIdx.x * blockDim.x + threadIdx.x;
    if (n >= Nn) return;
    atomicAdd(&gcnt[batch[n]], 1.0f);
}

// ------------------------------------------------------------------
// Final: out[g,p] = (gsum[g]/max(cnt,1)) @ lw + lb     (64 x 8)
// ------------------------------------------------------------------
__global__ void final_kernel(const float* __restrict__ gsum,
                             const float* __restrict__ gcnt,
                             const float* __restrict__ lw,
                             const float* __restrict__ lb,
                             float* __restrict__ out)
{
    int t = threadIdx.x;              // 512 threads
    if (t >= NGRAPH * NPRED) return;
    int g = t / NPRED;
    int p = t % NPRED;
    float inv = 1.0f / fmaxf(gcnt[g], 1.0f);
    float s = 0.f;
    for (int k = 0; k < HID; k++)
        s = fmaf(gsum[g * HID + k] * inv, lw[k * NPRED + p], s);
    out[t] = s + lb[p];
}

// ------------------------------------------------------------------
// Launch
// ------------------------------------------------------------------
static inline int cdiv(int a, int b) { return (a + b - 1) / b; }

extern "C" void kernel_launch(void* const* d_in, const int* in_sizes, int n_in,
                              void* d_out, int out_size)
{
    const float* x   = (const float*)d_in[0];
    const int*   ei  = (const int*)d_in[1];
    const float* ea  = (const float*)d_in[2];
    const int*   bat = (const int*)d_in[3];
    const float* mw1 = (const float*)d_in[4];
    const float* mb1 = (const float*)d_in[5];
    const float* mw2 = (const float*)d_in[6];
    const float* mb2 = (const float*)d_in[7];
    const float* mw3 = (const float*)d_in[8];
    const float* mb3 = (const float*)d_in[9];
    const float* mw4 = (const float*)d_in[10];
    const float* mb4 = (const float*)d_in[11];
    const float* nw1 = (const float*)d_in[12];
    const float* nb1 = (const float*)d_in[13];
    const float* nw2 = (const float*)d_in[14];
    const float* nb2 = (const float*)d_in[15];
    const float* nw3 = (const float*)d_in[16];
    const float* nb3 = (const float*)d_in[17];
    const float* nw4 = (const float*)d_in[18];
    const float* nb4 = (const float*)d_in[19];
    const float* lw  = (const float*)d_in[20];
    const float* lb  = (const float*)d_in[21];
    float* out = (float*)d_out;

    const int E  = in_sizes[1] / 2;       // edge_index is [2, E]
    const int Nn = in_sizes[0] / N_NF;    // x is [N, 16]
    const int* src = ei;                  // row 0
    const int* dst = ei + E;              // row 1

    float *feat, *buf1, *buf2, *aggr, *n1, *n2, *gsum, *gcnt;
    cudaGetSymbolAddress((void**)&feat, g_feat);
    cudaGetSymbolAddress((void**)&buf1, g_buf1);
    cudaGetSymbolAddress((void**)&buf2, g_buf2);
    cudaGetSymbolAddress((void**)&aggr, g_aggr);
    cudaGetSymbolAddress((void**)&n1,   g_n1);
    cudaGetSymbolAddress((void**)&n2,   g_n2);
    cudaGetSymbolAddress((void**)&gsum, g_gsum);
    cudaGetSymbolAddress((void**)&gcnt, g_gcnt);

    cudaMemsetAsync(aggr, 0, (size_t)N_NODES * MSGD * sizeof(float));
    cudaMemsetAsync(gsum, 0, (size_t)NGRAPH * HID * sizeof(float));
    cudaMemsetAsync(gcnt, 0, (size_t)NGRAPH * sizeof(float));

    // 1. Gather edge features [E, 40]
    {
        long long total = (long long)E * FEAT;
        gather_feat_kernel<<<(int)((total + 255) / 256), 256>>>(x, src, dst, ea, feat, E);
    }

    // 2. Edge (message) MLP: 40->300->300->300->128, layer 4 scatters to aggr
    {
        dim3 grid(cdiv(HID, BN), cdiv(E, BM));
        gemm_tf32<<<grid, 256>>>(feat, mw1, mb1, buf1, nullptr, E, FEAT, HID, 1);
        gemm_tf32<<<grid, 256>>>(buf1, mw2, mb2, buf2, nullptr, E, HID, HID, 1);
        gemm_tf32<<<grid, 256>>>(buf2, mw3, mb3, buf1, nullptr, E, HID, HID, 1);
        dim3 grid4(cdiv(MSGD, BN), cdiv(E, BM));
        gemm_tf32<<<grid4, 256>>>(buf1, mw4, mb4, aggr, dst, E, HID, MSGD, 0);
    }

    // 3. Node MLP: 128->300->300->300->300, layer 4 scatters to gsum (pool)
    {
        dim3 grid(cdiv(HID, BN), cdiv(Nn, BM));
        gemm_tf32<<<grid, 256>>>(aggr, nw1, nb1, n1, nullptr, Nn, MSGD, HID, 1);
        gemm_tf32<<<grid, 256>>>(n1,   nw2, nb2, n2, nullptr, Nn, HID,  HID, 1);
        gemm_tf32<<<grid, 256>>>(n2,   nw3, nb3, n1, nullptr, Nn, HID,  HID, 1);
        gemm_tf32<<<grid, 256>>>(n1,   nw4, nb4, gsum, bat,   Nn, HID,  HID, 0);
    }

    // 4. Counts + final linear
    pool_cnt_kernel<<<cdiv(Nn, 256), 256>>>(bat, gcnt, Nn);
    final_kernel<<<1, 512>>>(gsum, gcnt, lw, lb, out);
}

// round 5
// speedup vs baseline: 4.2498x; 1.0764x over previous
#include <cuda_runtime.h>
#include <cstdint>

// Problem constants (match reference)
#define E_CNT   800000
#define N_NODES 50000
#define N_NF    16
#define N_EF    8
#define FEAT    40      // 2*N_NF + N_EF
#define HID     300
#define MSGD    128
#define NGRAPH  64
#define NPRED   8

// ------------------------------------------------------------------
// Scratch (device globals)
// ------------------------------------------------------------------
__device__ float g_feat[(size_t)E_CNT * FEAT];
__device__ float g_buf1[(size_t)E_CNT * HID];
__device__ float g_buf2[(size_t)E_CNT * HID];
__device__ float g_aggr[(size_t)N_NODES * MSGD];
__device__ float g_n1[(size_t)N_NODES * HID];
__device__ float g_n2[(size_t)N_NODES * HID];
__device__ float g_gsum[NGRAPH * HID];
__device__ float g_gcnt[NGRAPH];
// rounded-weight scratch: mw1,mw2,mw3,mw4,nw1,nw2,nw3,nw4
#define W_TOTAL (40*300 + 300*300 + 300*300 + 300*128 + 128*300 + 300*300 + 300*300 + 300*300)
__device__ float g_wr[W_TOTAL];

__device__ __forceinline__ uint32_t f2tf32(float v) {
    uint32_t t;
    asm("cvt.rna.tf32.f32 %0, %1;" : "=r"(t) : "f"(v));
    return t;
}
__device__ __forceinline__ float round_tf32(float v) {
    return __uint_as_float(f2tf32(v));
}

// ------------------------------------------------------------------
// Round a weight matrix to tf32 (stored as fp32 with low bits zero)
// ------------------------------------------------------------------
__global__ void round_w_kernel(const float* __restrict__ src,
                               float* __restrict__ dst, int n)
{
    int i = blockIdx.x * blockDim.x + threadIdx.x;
    if (i < n) dst[i] = round_tf32(src[i]);
}

// ------------------------------------------------------------------
// Fused gather (rounded to tf32):
// feat[e] = rna(concat(x[dst[e]], x[src[e]], edge_attr[e]))
// ------------------------------------------------------------------
__global__ void gather_feat_kernel(const float* __restrict__ x,
                                   const int* __restrict__ src,
                                   const int* __restrict__ dst,
                                   const float* __restrict__ ea,
                                   float* __restrict__ feat, int E)
{
    long long idx = (long long)blockIdx.x * blockDim.x + threadIdx.x;
    long long total = (long long)E * FEAT;
    if (idx >= total) return;
    int e = (int)(idx / FEAT);
    int f = (int)(idx % FEAT);
    float v;
    if (f < N_NF) {
        v = x[(size_t)dst[e] * N_NF + f];
    } else if (f < 2 * N_NF) {
        v = x[(size_t)src[e] * N_NF + (f - N_NF)];
    } else {
        v = ea[(size_t)e * N_EF + (f - 2 * N_NF)];
    }
    feat[idx] = round_tf32(v);
}

// ------------------------------------------------------------------
// tf32 tensor-core GEMM, cp.async double-buffered.
// Inputs are pre-rounded to tf32 (raw bits fed to HMMA), except
// CVTA=1 which applies cvt.rna to A fragments (for non-tf32 A).
//   idx == nullptr : C[m,n] = v   (round_out? tf32-rounded)
//   idx != nullptr : atomicAdd(&C[idx[m]*N + n], v)  (raw fp32)
// Grid: x = N-tile (fastest -> A reuse in L2), y = M-tile.
// ------------------------------------------------------------------
#define BM 128
#define BN 64
#define BK 32

__device__ __forceinline__ void cp_async16(float* sptr, const float* gptr, bool pred)
{
    uint32_t saddr = (uint32_t)__cvta_generic_to_shared(sptr);
    int sz = pred ? 16 : 0;
    asm volatile("cp.async.cg.shared.global [%0], [%1], 16, %2;\n"
                 :: "r"(saddr), "l"(gptr), "r"(sz));
}
__device__ __forceinline__ void cp_async_commit() {
    asm volatile("cp.async.commit_group;\n" ::: "memory");
}
template<int N_> __device__ __forceinline__ void cp_async_wait() {
    asm volatile("cp.async.wait_group %0;\n" :: "n"(N_) : "memory");
}

template<int CVTA>
__global__ __launch_bounds__(256)
void gemm_tf32(const float* __restrict__ A,
               const float* __restrict__ W,
               const float* __restrict__ bias,
               float* __restrict__ C,
               const int* __restrict__ idx,
               int M, int K, int N, int do_relu, int round_out)
{
    __shared__ float As[2][BM][BK + 4];   // row stride 36 -> conflict-free frags
    __shared__ float Ws[2][BK][BN + 8];   // row stride 72 -> conflict-free frags

    const int tid  = threadIdx.x;
    const int warp = tid >> 5;
    const int lane = tid & 31;
    const int wm = (warp & 3) * 32;
    const int wn = (warp >> 2) * 32;
    const int n0 = blockIdx.x * BN;   // N-tile fastest => A reuse in L2
    const int m0 = blockIdx.y * BM;

    const int lr = lane >> 2;  // 0..7
    const int lc = lane & 3;   // 0..3

    // Per-thread cp.async chunk coordinates (A: 4 chunks, W: 2 chunks)
    int mmA[4], kcA[4];
    const float* agp[4];
    bool rowOkA[4];
#pragma unroll
    for (int i = 0; i < 4; i++) {
        int c = tid + i * 256;
        mmA[i] = c >> 3;           // 8 chunks per 32-float row
        kcA[i] = (c & 7) * 4;
        rowOkA[i] = (m0 + mmA[i]) < M;
        agp[i] = A + (size_t)(rowOkA[i] ? (m0 + mmA[i]) : 0) * K + kcA[i];
    }
    int kkW[2], ncW[2];
    const float* wgp[2];
    bool colOkW[2];
#pragma unroll
    for (int i = 0; i < 2; i++) {
        int c = tid + i * 256;
        kkW[i] = c >> 4;           // 16 chunks per 64-float row
        ncW[i] = (c & 15) * 4;
        colOkW[i] = (n0 + ncW[i]) < N;
        wgp[i] = W + (size_t)kkW[i] * N + n0 + ncW[i];
    }

    float acc[2][4][4];
#pragma unroll
    for (int mi = 0; mi < 2; mi++)
#pragma unroll
        for (int ni = 0; ni < 4; ni++)
#pragma unroll
            for (int r = 0; r < 4; r++) acc[mi][ni][r] = 0.f;

    const int nsteps = (K + BK - 1) / BK;

    // Prologue: load stage 0 into buffer 0
    {
#pragma unroll
        for (int i = 0; i < 4; i++)
            cp_async16(&As[0][mmA[i]][kcA[i]], agp[i], rowOkA[i] && (kcA[i] < K));
#pragma unroll
        for (int i = 0; i < 2; i++)
            cp_async16(&Ws[0][kkW[i]][ncW[i]], wgp[i], colOkW[i] && (kkW[i] < K));
        cp_async_commit();
    }

    for (int s = 0; s < nsteps; s++) {
        const int buf = s & 1;
        if (s + 1 < nsteps) {
            const int k0n = (s + 1) * BK;
            const int nb = buf ^ 1;
#pragma unroll
            for (int i = 0; i < 4; i++)
                cp_async16(&As[nb][mmA[i]][kcA[i]], agp[i] + k0n,
                           rowOkA[i] && (k0n + kcA[i] < K));
#pragma unroll
            for (int i = 0; i < 2; i++)
                cp_async16(&Ws[nb][kkW[i]][ncW[i]], wgp[i] + (size_t)k0n * N,
                           colOkW[i] && (k0n + kkW[i] < K));
            cp_async_commit();
            cp_async_wait<1>();
        } else {
            cp_async_wait<0>();
        }
        __syncthreads();

#pragma unroll
        for (int ks = 0; ks < BK; ks += 8) {
            uint32_t a[2][4], b[4][2];
#pragma unroll
            for (int mi = 0; mi < 2; mi++) {
                int mb = wm + mi * 16;
                if (CVTA) {
                    a[mi][0] = f2tf32(As[buf][mb + lr    ][ks + lc    ]);
                    a[mi][1] = f2tf32(As[buf][mb + lr + 8][ks + lc    ]);
                    a[mi][2] = f2tf32(As[buf][mb + lr    ][ks + lc + 4]);
                    a[mi][3] = f2tf32(As[buf][mb + lr + 8][ks + lc + 4]);
                } else {
                    a[mi][0] = __float_as_uint(As[buf][mb + lr    ][ks + lc    ]);
                    a[mi][1] = __float_as_uint(As[buf][mb + lr + 8][ks + lc    ]);
                    a[mi][2] = __float_as_uint(As[buf][mb + lr    ][ks + lc + 4]);
                    a[mi][3] = __float_as_uint(As[buf][mb + lr + 8][ks + lc + 4]);
                }
            }
#pragma unroll
            for (int ni = 0; ni < 4; ni++) {
                int nb = wn + ni * 8;
                b[ni][0] = __float_as_uint(Ws[buf][ks + lc    ][nb + lr]);
                b[ni][1] = __float_as_uint(Ws[buf][ks + lc + 4][nb + lr]);
            }
#pragma unroll
            for (int mi = 0; mi < 2; mi++)
#pragma unroll
                for (int ni = 0; ni < 4; ni++) {
                    asm volatile(
                        "mma.sync.aligned.m16n8k8.row.col.f32.tf32.tf32.f32 "
                        "{%0,%1,%2,%3}, {%4,%5,%6,%7}, {%8,%9}, {%0,%1,%2,%3};\n"
                        : "+f"(acc[mi][ni][0]), "+f"(acc[mi][ni][1]),
                          "+f"(acc[mi][ni][2]), "+f"(acc[mi][ni][3])
                        : "r"(a[mi][0]), "r"(a[mi][1]), "r"(a[mi][2]), "r"(a[mi][3]),
                          "r"(b[ni][0]), "r"(b[ni][1]));
                }
        }
        __syncthreads();  // protect buf before next iteration's cp.async reuses it
    }

    // Epilogue: bias (+ReLU), optional tf32 rounding, store or scatter.
#pragma unroll
    for (int mi = 0; mi < 2; mi++) {
#pragma unroll
        for (int half = 0; half < 2; half++) {
            int row = m0 + wm + mi * 16 + lr + half * 8;
            if (row >= M) continue;
            long long obase;
            if (idx) obase = (long long)idx[row] * N;
            else     obase = (long long)row * N;
#pragma unroll
            for (int ni = 0; ni < 4; ni++) {
                int col = n0 + wn + ni * 8 + lc * 2;
#pragma unroll
                for (int q = 0; q < 2; q++) {
                    if (col + q >= N) continue;
                    float v = acc[mi][ni][half * 2 + q] + bias[col + q];
                    if (do_relu) v = fmaxf(v, 0.f);
                    if (round_out) v = round_tf32(v);
                    if (idx) atomicAdd(&C[obase + col + q], v);
                    else     C[obase + col + q] = v;
                }
            }
        }
    }
}

// ------------------------------------------------------------------
// Pool count: gcnt[batch[n]] += 1
// ------------------------------------------------------------------
__global__ void pool_cnt_kernel(const int* __restrict__ batch,
                                float* __restrict__ gcnt, int Nn)
{
    int n = blockIdx.x * blockDim.x + threadIdx.x;
    if (n >= Nn) return;
    atomicAdd(&gcnt[batch[n]], 1.0f);
}

// ------------------------------------------------------------------
// Final: out[g,p] = (gsum[g]/max(cnt,1)) @ lw + lb     (64 x 8)
// ------------------------------------------------------------------
__global__ void final_kernel(const float* __restrict__ gsum,
                             const float* __restrict__ gcnt,
                             const float* __restrict__ lw,
                             const float* __restrict__ lb,
                             float* __restrict__ out)
{
    int t = threadIdx.x;              // 512 threads
    if (t >= NGRAPH * NPRED) return;
    int g = t / NPRED;
    int p = t % NPRED;
    float inv = 1.0f / fmaxf(gcnt[g], 1.0f);
    float s = 0.f;
    for (int k = 0; k < HID; k++)
        s = fmaf(gsum[g * HID + k] * inv, lw[k * NPRED + p], s);
    out[t] = s + lb[p];
}

// ------------------------------------------------------------------
// Launch
// ------------------------------------------------------------------
static inline int cdiv(int a, int b) { return (a + b - 1) / b; }

extern "C" void kernel_launch(void* const* d_in, const int* in_sizes, int n_in,
                              void* d_out, int out_size)
{
    const float* x   = (const float*)d_in[0];
    const int*   ei  = (const int*)d_in[1];
    const float* ea  = (const float*)d_in[2];
    const int*   bat = (const int*)d_in[3];
    const float* mw1 = (const float*)d_in[4];
    const float* mb1 = (const float*)d_in[5];
    const float* mw2 = (const float*)d_in[6];
    const float* mb2 = (const float*)d_in[7];
    const float* mw3 = (const float*)d_in[8];
    const float* mb3 = (const float*)d_in[9];
    const float* mw4 = (const float*)d_in[10];
    const float* mb4 = (const float*)d_in[11];
    const float* nw1 = (const float*)d_in[12];
    const float* nb1 = (const float*)d_in[13];
    const float* nw2 = (const float*)d_in[14];
    const float* nb2 = (const float*)d_in[15];
    const float* nw3 = (const float*)d_in[16];
    const float* nb3 = (const float*)d_in[17];
    const float* nw4 = (const float*)d_in[18];
    const float* nb4 = (const float*)d_in[19];
    const float* lw  = (const float*)d_in[20];
    const float* lb  = (const float*)d_in[21];
    float* out = (float*)d_out;

    const int E  = in_sizes[1] / 2;       // edge_index is [2, E]
    const int Nn = in_sizes[0] / N_NF;    // x is [N, 16]
    const int* src = ei;                  // row 0
    const int* dst = ei + E;              // row 1

    float *feat, *buf1, *buf2, *aggr, *n1, *n2, *gsum, *gcnt, *wr;
    cudaGetSymbolAddress((void**)&feat, g_feat);
    cudaGetSymbolAddress((void**)&buf1, g_buf1);
    cudaGetSymbolAddress((void**)&buf2, g_buf2);
    cudaGetSymbolAddress((void**)&aggr, g_aggr);
    cudaGetSymbolAddress((void**)&n1,   g_n1);
    cudaGetSymbolAddress((void**)&n2,   g_n2);
    cudaGetSymbolAddress((void**)&gsum, g_gsum);
    cudaGetSymbolAddress((void**)&gcnt, g_gcnt);
    cudaGetSymbolAddress((void**)&wr,   g_wr);

    // Rounded-weight scratch layout
    float* wr_mw1 = wr;                         // 40*300
    float* wr_mw2 = wr_mw1 + 40 * 300;          // 300*300
    float* wr_mw3 = wr_mw2 + 300 * 300;
    float* wr_mw4 = wr_mw3 + 300 * 300;         // 300*128
    float* wr_nw1 = wr_mw4 + 300 * 128;         // 128*300
    float* wr_nw2 = wr_nw1 + 128 * 300;
    float* wr_nw3 = wr_nw2 + 300 * 300;
    float* wr_nw4 = wr_nw3 + 300 * 300;

    cudaMemsetAsync(aggr, 0, (size_t)N_NODES * MSGD * sizeof(float));
    cudaMemsetAsync(gsum, 0, (size_t)NGRAPH * HID * sizeof(float));
    cudaMemsetAsync(gcnt, 0, (size_t)NGRAPH * sizeof(float));

    // 0. Round weights to tf32 once
    round_w_kernel<<<cdiv(40 * 300, 256), 256>>>(mw1, wr_mw1, 40 * 300);
    round_w_kernel<<<cdiv(300 * 300, 256), 256>>>(mw2, wr_mw2, 300 * 300);
    round_w_kernel<<<cdiv(300 * 300, 256), 256>>>(mw3, wr_mw3, 300 * 300);
    round_w_kernel<<<cdiv(300 * 128, 256), 256>>>(mw4, wr_mw4, 300 * 128);
    round_w_kernel<<<cdiv(128 * 300, 256), 256>>>(nw1, wr_nw1, 128 * 300);
    round_w_kernel<<<cdiv(300 * 300, 256), 256>>>(nw2, wr_nw2, 300 * 300);
    round_w_kernel<<<cdiv(300 * 300, 256), 256>>>(nw3, wr_nw3, 300 * 300);
    round_w_kernel<<<cdiv(300 * 300, 256), 256>>>(nw4, wr_nw4, 300 * 300);

    // 1. Gather edge features [E, 40] (tf32-rounded)
    {
        long long total = (long long)E * FEAT;
        gather_feat_kernel<<<(int)((total + 255) / 256), 256>>>(x, src, dst, ea, feat, E);
    }

    // 2. Edge MLP: 40->300->300->300->128, layer 4 scatters raw into aggr
    {
        dim3 grid(cdiv(HID, BN), cdiv(E, BM));
        gemm_tf32<0><<<grid, 256>>>(feat, wr_mw1, mb1, buf1, nullptr, E, FEAT, HID, 1, 1);
        gemm_tf32<0><<<grid, 256>>>(buf1, wr_mw2, mb2, buf2, nullptr, E, HID, HID, 1, 1);
        gemm_tf32<0><<<grid, 256>>>(buf2, wr_mw3, mb3, buf1, nullptr, E, HID, HID, 1, 1);
        dim3 grid4(cdiv(MSGD, BN), cdiv(E, BM));
        gemm_tf32<0><<<grid4, 256>>>(buf1, wr_mw4, mb4, aggr, dst, E, HID, MSGD, 0, 0);
    }

    // 3. Node MLP: 128->300->300->300->300; layer 1 cvts A (aggr is raw fp32
    //    sums); layer 4 scatters raw into gsum (pool)
    {
        dim3 grid(cdiv(HID, BN), cdiv(Nn, BM));
        gemm_tf32<1><<<grid, 256>>>(aggr, wr_nw1, nb1, n1, nullptr, Nn, MSGD, HID, 1, 1);
        gemm_tf32<0><<<grid, 256>>>(n1,   wr_nw2, nb2, n2, nullptr, Nn, HID,  HID, 1, 1);
        gemm_tf32<0><<<grid, 256>>>(n2,   wr_nw3, nb3, n1, nullptr, Nn, HID,  HID, 1, 1);
        gemm_tf32<0><<<grid, 256>>>(n1,   wr_nw4, nb4, gsum, bat,   Nn, HID,  HID, 0, 0);
    }

    // 4. Counts + final linear
    pool_cnt_kernel<<<cdiv(Nn, 256), 256>>>(bat, gcnt, Nn);
    final_kernel<<<1, 512>>>(gsum, gcnt, lw, lb, out);
}

// round 6
// speedup vs baseline: 4.3258x; 1.0179x over previous
#include <cuda_runtime.h>
#include <cstdint>

// Problem constants (match reference)
#define E_CNT   800000
#define N_NODES 50000
#define N_NF    16
#define N_EF    8
#define FEAT    40      // 2*N_NF + N_EF
#define HID     300
#define MSGD    128
#define NGRAPH  64
#define NPRED   8

// ------------------------------------------------------------------
// Scratch (device globals)
// ------------------------------------------------------------------
__device__ float g_feat[(size_t)E_CNT * FEAT];
__device__ float g_buf1[(size_t)E_CNT * HID];
__device__ float g_buf2[(size_t)E_CNT * HID];
__device__ float g_aggr[(size_t)N_NODES * MSGD];
__device__ float g_n1[(size_t)N_NODES * HID];
__device__ float g_n2[(size_t)N_NODES * HID];
__device__ float g_gsum[NGRAPH * HID];
__device__ float g_gcnt[NGRAPH];
// rounded+TRANSPOSED weight scratch: each stored as W^T [N][K]
#define W_TOTAL (40*300 + 300*300 + 300*300 + 300*128 + 128*300 + 300*300 + 300*300 + 300*300)
__device__ float g_wr[W_TOTAL];

__device__ __forceinline__ uint32_t f2tf32(float v) {
    uint32_t t;
    asm("cvt.rna.tf32.f32 %0, %1;" : "=r"(t) : "f"(v));
    return t;
}
__device__ __forceinline__ float round_tf32(float v) {
    return __uint_as_float(f2tf32(v));
}

// ------------------------------------------------------------------
// Round W [K,N] to tf32 and transpose to W^T [N,K]
// ------------------------------------------------------------------
__global__ void round_wT_kernel(const float* __restrict__ src,
                                float* __restrict__ dst, int K, int N)
{
    int i = blockIdx.x * blockDim.x + threadIdx.x;
    if (i >= K * N) return;
    int k = i / N, n = i % N;
    dst[(size_t)n * K + k] = round_tf32(src[i]);
}

// ------------------------------------------------------------------
// Fused gather (rounded to tf32)
// ------------------------------------------------------------------
__global__ void gather_feat_kernel(const float* __restrict__ x,
                                   const int* __restrict__ src,
                                   const int* __restrict__ dst,
                                   const float* __restrict__ ea,
                                   float* __restrict__ feat, int E)
{
    long long idx = (long long)blockIdx.x * blockDim.x + threadIdx.x;
    long long total = (long long)E * FEAT;
    if (idx >= total) return;
    int e = (int)(idx / FEAT);
    int f = (int)(idx % FEAT);
    float v;
    if (f < N_NF) {
        v = x[(size_t)dst[e] * N_NF + f];
    } else if (f < 2 * N_NF) {
        v = x[(size_t)src[e] * N_NF + (f - N_NF)];
    } else {
        v = ea[(size_t)e * N_EF + (f - 2 * N_NF)];
    }
    feat[idx] = round_tf32(v);
}

// ------------------------------------------------------------------
// tf32 tensor-core GEMM, cp.async double-buffered, ldmatrix fragments.
// C[M,N] = act(A[M,K] @ W[K,N] + bias); W passed TRANSPOSED as Wt[N,K].
//   idx == nullptr : C[m,n] = v   (round_out? tf32-rounded)
//   idx != nullptr : atomicAdd(&C[idx[m]*N + n], v)  (raw fp32)
// Grid: x = N-tile (fastest -> A reuse in L2), y = M-tile.
// BM=128, BN=64, BK=32; 8 warps 4(M)x2(N); warp tile 32x32.
// Per 8-k-step: 4 ldmatrix.x4 + 8 HMMA (was 16 LDS + 8 HMMA).
// ------------------------------------------------------------------
#define BM 128
#define BN 64
#define BK 32
#define SSTRIDE 36   // floats per smem row; 144B = 9*16B (LDSM-aligned, conflict-free)

__device__ __forceinline__ void cp_async16(float* sptr, const float* gptr, bool pred)
{
    uint32_t saddr = (uint32_t)__cvta_generic_to_shared(sptr);
    int sz = pred ? 16 : 0;
    asm volatile("cp.async.cg.shared.global [%0], [%1], 16, %2;\n"
                 :: "r"(saddr), "l"(gptr), "r"(sz));
}
__device__ __forceinline__ void cp_async_commit() {
    asm volatile("cp.async.commit_group;\n" ::: "memory");
}
template<int N_> __device__ __forceinline__ void cp_async_wait() {
    asm volatile("cp.async.wait_group %0;\n" :: "n"(N_) : "memory");
}
__device__ __forceinline__ void ldsm_x4(uint32_t& r0, uint32_t& r1,
                                        uint32_t& r2, uint32_t& r3, uint32_t saddr)
{
    asm volatile("ldmatrix.sync.aligned.m8n8.x4.shared.b16 {%0,%1,%2,%3}, [%4];\n"
                 : "=r"(r0), "=r"(r1), "=r"(r2), "=r"(r3) : "r"(saddr));
}

template<int CVTA>
__global__ __launch_bounds__(256)
void gemm_tf32(const float* __restrict__ A,
               const float* __restrict__ Wt,     // [N, K] transposed weights
               const float* __restrict__ bias,
               float* __restrict__ C,
               const int* __restrict__ idx,
               int M, int K, int N, int do_relu, int round_out)
{
    __shared__ __align__(16) float As[2][BM][SSTRIDE];
    __shared__ __align__(16) float Ws[2][BN][SSTRIDE];   // Ws[n][k]

    const int tid  = threadIdx.x;
    const int warp = tid >> 5;
    const int lane = tid & 31;
    const int wm = (warp & 3) * 32;
    const int wn = (warp >> 2) * 32;
    const int n0 = blockIdx.x * BN;   // N-tile fastest => A reuse in L2
    const int m0 = blockIdx.y * BM;

    const int lr = lane >> 2;  // 0..7
    const int lc = lane & 3;   // 0..3

    // ldmatrix address roles: t = which 8x8 tile this thread addresses
    const int t8 = lane >> 3;      // 0..3
    const int r8 = lane & 7;       // 0..7
    // A tiles: t0:(rows+0..7,k+0..3) t1:(rows+8..15,k+0..3) t2:(+0..7,k+4..7) t3:(+8..15,k+4..7)
    const int aRowOff = ((t8 & 1) << 3) + r8;      // + wm + mi*16
    const int aColOff = (t8 >> 1) << 2;            // + ks
    // B tiles: t0:(n+0..7,k+0..3) t1:(n+0..7,k+4..7) t2:(n+8..15,k+0..3) t3:(n+8..15,k+4..7)
    const int bRowOff = ((t8 >> 1) << 3) + r8;     // + wn + p*16
    const int bColOff = (t8 & 1) << 2;             // + ks

    const uint32_t As32 = (uint32_t)__cvta_generic_to_shared(&As[0][0][0]);
    const uint32_t Ws32 = (uint32_t)__cvta_generic_to_shared(&Ws[0][0][0]);

    // cp.async chunk coordinates: A = 4 chunks/thread, Wt = 2 chunks/thread
    int mmA[4], kcA[4];
    const float* agp[4];
    bool rowOkA[4];
#pragma unroll
    for (int i = 0; i < 4; i++) {
        int c = tid + i * 256;
        mmA[i] = c >> 3;           // 8 chunks per 32-float row
        kcA[i] = (c & 7) * 4;
        rowOkA[i] = (m0 + mmA[i]) < M;
        agp[i] = A + (size_t)(rowOkA[i] ? (m0 + mmA[i]) : 0) * K + kcA[i];
    }
    int nnW[2], kcW[2];
    const float* wgp[2];
    bool rowOkW[2];
#pragma unroll
    for (int i = 0; i < 2; i++) {
        int c = tid + i * 256;
        nnW[i] = c >> 3;           // 8 chunks per 32-float row
        kcW[i] = (c & 7) * 4;
        rowOkW[i] = (n0 + nnW[i]) < N;
        wgp[i] = Wt + (size_t)(rowOkW[i] ? (n0 + nnW[i]) : 0) * K + kcW[i];
    }

    float acc[2][4][4];
#pragma unroll
    for (int mi = 0; mi < 2; mi++)
#pragma unroll
        for (int ni = 0; ni < 4; ni++)
#pragma unroll
            for (int r = 0; r < 4; r++) acc[mi][ni][r] = 0.f;

    const int nsteps = (K + BK - 1) / BK;

    // Prologue: stage 0 -> buffer 0
    {
#pragma unroll
        for (int i = 0; i < 4; i++)
            cp_async16(&As[0][mmA[i]][kcA[i]], agp[i], rowOkA[i] && (kcA[i] < K));
#pragma unroll
        for (int i = 0; i < 2; i++)
            cp_async16(&Ws[0][nnW[i]][kcW[i]], wgp[i], rowOkW[i] && (kcW[i] < K));
        cp_async_commit();
    }

    for (int s = 0; s < nsteps; s++) {
        const int buf = s & 1;
        if (s + 1 < nsteps) {
            const int k0n = (s + 1) * BK;
            const int nb = buf ^ 1;
#pragma unroll
            for (int i = 0; i < 4; i++)
                cp_async16(&As[nb][mmA[i]][kcA[i]], agp[i] + k0n,
                           rowOkA[i] && (k0n + kcA[i] < K));
#pragma unroll
            for (int i = 0; i < 2; i++)
                cp_async16(&Ws[nb][nnW[i]][kcW[i]], wgp[i] + k0n,
                           rowOkW[i] && (k0n + kcW[i] < K));
            cp_async_commit();
            cp_async_wait<1>();
        } else {
            cp_async_wait<0>();
        }
        __syncthreads();

        const uint32_t aBufBase = As32 + (uint32_t)buf * (BM * SSTRIDE * 4);
        const uint32_t wBufBase = Ws32 + (uint32_t)buf * (BN * SSTRIDE * 4);

#pragma unroll
        for (int ks = 0; ks < BK; ks += 8) {
            uint32_t a[2][4], b[4][2];
#pragma unroll
            for (int mi = 0; mi < 2; mi++) {
                uint32_t addr = aBufBase +
                    (uint32_t)(((wm + mi * 16 + aRowOff) * SSTRIDE + ks + aColOff) * 4);
                ldsm_x4(a[mi][0], a[mi][1], a[mi][2], a[mi][3], addr);
                if (CVTA) {
#pragma unroll
                    for (int q = 0; q < 4; q++)
                        a[mi][q] = f2tf32(__uint_as_float(a[mi][q]));
                }
            }
#pragma unroll
            for (int p = 0; p < 2; p++) {
                uint32_t addr = wBufBase +
                    (uint32_t)(((wn + p * 16 + bRowOff) * SSTRIDE + ks + bColOff) * 4);
                ldsm_x4(b[2 * p][0], b[2 * p][1], b[2 * p + 1][0], b[2 * p + 1][1], addr);
            }
#pragma unroll
            for (int mi = 0; mi < 2; mi++)
#pragma unroll
                for (int ni = 0; ni < 4; ni++) {
                    asm volatile(
                        "mma.sync.aligned.m16n8k8.row.col.f32.tf32.tf32.f32 "
                        "{%0,%1,%2,%3}, {%4,%5,%6,%7}, {%8,%9}, {%0,%1,%2,%3};\n"
                        : "+f"(acc[mi][ni][0]), "+f"(acc[mi][ni][1]),
                          "+f"(acc[mi][ni][2]), "+f"(acc[mi][ni][3])
                        : "r"(a[mi][0]), "r"(a[mi][1]), "r"(a[mi][2]), "r"(a[mi][3]),
                          "r"(b[ni][0]), "r"(b[ni][1]));
                }
        }
        __syncthreads();  // all warps done with buf before next cp.async overwrites it
    }

    // Epilogue: bias (+ReLU), optional tf32 rounding, store or scatter.
#pragma unroll
    for (int mi = 0; mi < 2; mi++) {
#pragma unroll
        for (int half = 0; half < 2; half++) {
            int row = m0 + wm + mi * 16 + lr + half * 8;
            if (row >= M) continue;
            long long obase;
            if (idx) obase = (long long)idx[row] * N;
            else     obase = (long long)row * N;
#pragma unroll
            for (int ni = 0; ni < 4; ni++) {
                int col = n0 + wn + ni * 8 + lc * 2;
#pragma unroll
                for (int q = 0; q < 2; q++) {
                    if (col + q >= N) continue;
                    float v = acc[mi][ni][half * 2 + q] + bias[col + q];
                    if (do_relu) v = fmaxf(v, 0.f);
                    if (round_out) v = round_tf32(v);
                    if (idx) atomicAdd(&C[obase + col + q], v);
                    else     C[obase + col + q] = v;
                }
            }
        }
    }
}

// ------------------------------------------------------------------
// Pool count: gcnt[batch[n]] += 1
// ------------------------------------------------------------------
__global__ void pool_cnt_kernel(const int* __restrict__ batch,
                                float* __restrict__ gcnt, int Nn)
{
    int n = blockIdx.x * blockDim.x + threadIdx.x;
    if (n >= Nn) return;
    atomicAdd(&gcnt[batch[n]], 1.0f);
}

// ------------------------------------------------------------------
// Final: out[g,p] = (gsum[g]/max(cnt,1)) @ lw + lb     (64 x 8)
// ------------------------------------------------------------------
__global__ void final_kernel(const float* __restrict__ gsum,
                             const float* __restrict__ gcnt,
                             const float* __restrict__ lw,
                             const float* __restrict__ lb,
                             float* __restrict__ out)
{
    int t = threadIdx.x;              // 512 threads
    if (t >= NGRAPH * NPRED) return;
    int g = t / NPRED;
    int p = t % NPRED;
    float inv = 1.0f / fmaxf(gcnt[g], 1.0f);
    float s = 0.f;
    for (int k = 0; k < HID; k++)
        s = fmaf(gsum[g * HID + k] * inv, lw[k * NPRED + p], s);
    out[t] = s + lb[p];
}

// ------------------------------------------------------------------
// Launch
// ------------------------------------------------------------------
static inline int cdiv(int a, int b) { return (a + b - 1) / b; }

extern "C" void kernel_launch(void* const* d_in, const int* in_sizes, int n_in,
                              void* d_out, int out_size)
{
    const float* x   = (const float*)d_in[0];
    const int*   ei  = (const int*)d_in[1];
    const float* ea  = (const float*)d_in[2];
    const int*   bat = (const int*)d_in[3];
    const float* mw1 = (const float*)d_in[4];
    const float* mb1 = (const float*)d_in[5];
    const float* mw2 = (const float*)d_in[6];
    const float* mb2 = (const float*)d_in[7];
    const float* mw3 = (const float*)d_in[8];
    const float* mb3 = (const float*)d_in[9];
    const float* mw4 = (const float*)d_in[10];
    const float* mb4 = (const float*)d_in[11];
    const float* nw1 = (const float*)d_in[12];
    const float* nb1 = (const float*)d_in[13];
    const float* nw2 = (const float*)d_in[14];
    const float* nb2 = (const float*)d_in[15];
    const float* nw3 = (const float*)d_in[16];
    const float* nb3 = (const float*)d_in[17];
    const float* nw4 = (const float*)d_in[18];
    const float* nb4 = (const float*)d_in[19];
    const float* lw  = (const float*)d_in[20];
    const float* lb  = (const float*)d_in[21];
    float* out = (float*)d_out;

    const int E  = in_sizes[1] / 2;       // edge_index is [2, E]
    const int Nn = in_sizes[0] / N_NF;    // x is [N, 16]
    const int* src = ei;                  // row 0
    const int* dst = ei + E;              // row 1

    float *feat, *buf1, *buf2, *aggr, *n1, *n2, *gsum, *gcnt, *wr;
    cudaGetSymbolAddress((void**)&feat, g_feat);
    cudaGetSymbolAddress((void**)&buf1, g_buf1);
    cudaGetSymbolAddress((void**)&buf2, g_buf2);
    cudaGetSymbolAddress((void**)&aggr, g_aggr);
    cudaGetSymbolAddress((void**)&n1,   g_n1);
    cudaGetSymbolAddress((void**)&n2,   g_n2);
    cudaGetSymbolAddress((void**)&gsum, g_gsum);
    cudaGetSymbolAddress((void**)&gcnt, g_gcnt);
    cudaGetSymbolAddress((void**)&wr,   g_wr);

    // Rounded+transposed weight scratch layout (each W^T is [N][K])
    float* wr_mw1 = wr;                         // [300][40]
    float* wr_mw2 = wr_mw1 + 40 * 300;          // [300][300]
    float* wr_mw3 = wr_mw2 + 300 * 300;
    float* wr_mw4 = wr_mw3 + 300 * 300;         // [128][300]
    float* wr_nw1 = wr_mw4 + 300 * 128;         // [300][128]
    float* wr_nw2 = wr_nw1 + 128 * 300;
    float* wr_nw3 = wr_nw2 + 300 * 300;
    float* wr_nw4 = wr_nw3 + 300 * 300;

    cudaMemsetAsync(aggr, 0, (size_t)N_NODES * MSGD * sizeof(float));
    cudaMemsetAsync(gsum, 0, (size_t)NGRAPH * HID * sizeof(float));
    cudaMemsetAsync(gcnt, 0, (size_t)NGRAPH * sizeof(float));

    // 0. Round + transpose weights once
    round_wT_kernel<<<cdiv(40 * 300, 256), 256>>>(mw1, wr_mw1, 40, 300);
    round_wT_kernel<<<cdiv(300 * 300, 256), 256>>>(mw2, wr_mw2, 300, 300);
    round_wT_kernel<<<cdiv(300 * 300, 256), 256>>>(mw3, wr_mw3, 300, 300);
    round_wT_kernel<<<cdiv(300 * 128, 256), 256>>>(mw4, wr_mw4, 300, 128);
    round_wT_kernel<<<cdiv(128 * 300, 256), 256>>>(nw1, wr_nw1, 128, 300);
    round_wT_kernel<<<cdiv(300 * 300, 256), 256>>>(nw2, wr_nw2, 300, 300);
    round_wT_kernel<<<cdiv(300 * 300, 256), 256>>>(nw3, wr_nw3, 300, 300);
    round_wT_kernel<<<cdiv(300 * 300, 256), 256>>>(nw4, wr_nw4, 300, 300);

    // 1. Gather edge features [E, 40] (tf32-rounded)
    {
        long long total = (long long)E * FEAT;
        gather_feat_kernel<<<(int)((total + 255) / 256), 256>>>(x, src, dst, ea, feat, E);
    }

    // 2. Edge MLP: 40->300->300->300->128, layer 4 scatters raw into aggr
    {
        dim3 grid(cdiv(HID, BN), cdiv(E, BM));
        gemm_tf32<0><<<grid, 256>>>(feat, wr_mw1, mb1, buf1, nullptr, E, FEAT, HID, 1, 1);
        gemm_tf32<0><<<grid, 256>>>(buf1, wr_mw2, mb2, buf2, nullptr, E, HID, HID, 1, 1);
        gemm_tf32<0><<<grid, 256>>>(buf2, wr_mw3, mb3, buf1, nullptr, E, HID, HID, 1, 1);
        dim3 grid4(cdiv(MSGD, BN), cdiv(E, BM));
        gemm_tf32<0><<<grid4, 256>>>(buf1, wr_mw4, mb4, aggr, dst, E, HID, MSGD, 0, 0);
    }

    // 3. Node MLP: 128->300->300->300->300; layer 1 cvts A fragments
    //    (aggr holds raw fp32 sums); layer 4 scatters raw into gsum (pool)
    {
        dim3 grid(cdiv(HID, BN), cdiv(Nn, BM));
        gemm_tf32<1><<<grid, 256>>>(aggr, wr_nw1, nb1, n1, nullptr, Nn, MSGD, HID, 1, 1);
        gemm_tf32<0><<<grid, 256>>>(n1,   wr_nw2, nb2, n2, nullptr, Nn, HID,  HID, 1, 1);
        gemm_tf32<0><<<grid, 256>>>(n2,   wr_nw3, nb3, n1, nullptr, Nn, HID,  HID, 1, 1);
        gemm_tf32<0><<<grid, 256>>>(n1,   wr_nw4, nb4, gsum, bat,   Nn, HID,  HID, 0, 0);
    }

    // 4. Counts + final linear
    pool_cnt_kernel<<<cdiv(Nn, 256), 256>>>(bat, gcnt, Nn);
    final_kernel<<<1, 512>>>(gsum, gcnt, lw, lb, out);
}

// round 7
// speedup vs baseline: 7.1053x; 1.6426x over previous
#include <cuda_runtime.h>
#include <cuda_bf16.h>
#include <cstdint>

// Problem constants (match reference)
#define E_CNT   800000
#define N_NODES 50000
#define N_NF    16
#define N_EF    8
#define FEAT    40      // 2*N_NF + N_EF
#define FEATP   48      // padded to 8-half chunks
#define HID     300
#define HIDP    304     // padded
#define MSGD    128
#define NGRAPH  64
#define NPRED   8

// ------------------------------------------------------------------
// Scratch (device globals; zero-initialized at module load, pads stay 0)
// ------------------------------------------------------------------
__device__ __nv_bfloat16 g_featb[(size_t)E_CNT * FEATP];
__device__ __nv_bfloat16 g_bbuf1[(size_t)E_CNT * HIDP];
__device__ __nv_bfloat16 g_bbuf2[(size_t)E_CNT * HIDP];
__device__ float g_aggr[(size_t)N_NODES * MSGD];
__device__ float g_n1[(size_t)N_NODES * HID];
__device__ float g_n2[(size_t)N_NODES * HID];
__device__ float g_gsum[NGRAPH * HID];
__device__ float g_gcnt[NGRAPH];
// edge weights: bf16, transposed+padded [N][Kp]
#define WBF_TOTAL (300*FEATP + 300*HIDP + 300*HIDP + 128*HIDP)
__device__ __nv_bfloat16 g_wbf[WBF_TOTAL];
// node weights: fp32 tf32-rounded, transposed [N][K]
#define WND_TOTAL (300*128 + 300*300 + 300*300 + 300*300)
__device__ float g_wnd[WND_TOTAL];

__device__ __forceinline__ uint32_t f2tf32(float v) {
    uint32_t t;
    asm("cvt.rna.tf32.f32 %0, %1;" : "=r"(t) : "f"(v));
    return t;
}
__device__ __forceinline__ float round_tf32(float v) {
    return __uint_as_float(f2tf32(v));
}

// ------------------------------------------------------------------
// Weight prep kernels
// ------------------------------------------------------------------
__global__ void prep_wbf_kernel(const float* __restrict__ src,   // [K][N]
                                __nv_bfloat16* __restrict__ dst, // [N][Kp]
                                int K, int N, int Kp)
{
    int i = blockIdx.x * blockDim.x + threadIdx.x;
    if (i >= N * Kp) return;
    int n = i / Kp, k = i % Kp;
    dst[i] = (k < K) ? __float2bfloat16(src[(size_t)k * N + n])
                     : __float2bfloat16(0.f);
}

__global__ void round_wT_kernel(const float* __restrict__ src,  // [K][N]
                                float* __restrict__ dst,        // [N][K]
                                int K, int N)
{
    int i = blockIdx.x * blockDim.x + threadIdx.x;
    if (i >= K * N) return;
    int k = i / N, n = i % N;
    dst[(size_t)n * K + k] = round_tf32(src[i]);
}

// ------------------------------------------------------------------
// Fused gather -> bf16 feat [E][FEATP] (pads stay zero)
// ------------------------------------------------------------------
__global__ void gather_feat_kernel(const float* __restrict__ x,
                                   const int* __restrict__ src,
                                   const int* __restrict__ dst,
                                   const float* __restrict__ ea,
                                   __nv_bfloat16* __restrict__ feat, int E)
{
    long long idx = (long long)blockIdx.x * blockDim.x + threadIdx.x;
    long long total = (long long)E * FEAT;
    if (idx >= total) return;
    int e = (int)(idx / FEAT);
    int f = (int)(idx % FEAT);
    float v;
    if (f < N_NF) {
        v = x[(size_t)dst[e] * N_NF + f];
    } else if (f < 2 * N_NF) {
        v = x[(size_t)src[e] * N_NF + (f - N_NF)];
    } else {
        v = ea[(size_t)e * N_EF + (f - 2 * N_NF)];
    }
    feat[(size_t)e * FEATP + f] = __float2bfloat16(v);
}

// ------------------------------------------------------------------
// Shared async-copy helpers
// ------------------------------------------------------------------
__device__ __forceinline__ void cp_async16(void* sptr, const void* gptr, bool pred)
{
    uint32_t saddr = (uint32_t)__cvta_generic_to_shared(sptr);
    int sz = pred ? 16 : 0;  // src-size 0 => 16B of zeros written
    asm volatile("cp.async.cg.shared.global [%0], [%1], 16, %2;\n"
                 :: "r"(saddr), "l"(gptr), "r"(sz));
}
__device__ __forceinline__ void cp_async_commit() {
    asm volatile("cp.async.commit_group;\n" ::: "memory");
}
template<int N_> __device__ __forceinline__ void cp_async_wait() {
    asm volatile("cp.async.wait_group %0;\n" :: "n"(N_) : "memory");
}
__device__ __forceinline__ void ldsm_x4(uint32_t& r0, uint32_t& r1,
                                        uint32_t& r2, uint32_t& r3, uint32_t saddr)
{
    asm volatile("ldmatrix.sync.aligned.m8n8.x4.shared.b16 {%0,%1,%2,%3}, [%4];\n"
                 : "=r"(r0), "=r"(r1), "=r"(r2), "=r"(r3) : "r"(saddr));
}

#define BM 128
#define BN 64

// ==================================================================
// bf16 GEMM (edge MLP): C[M,N] = act(A[M,Kp] @ W + bias)
// A bf16 [M][lda], Wt bf16 [N][Kp]; Kp multiple of 8 (zero-padded).
// SCATTER=0: store bf16 to C (ldc stride); SCATTER=1: atomicAdd fp32
// into C[idx[m]*ldc + n].
// BK=64 halves; 8 warps 4(M)x2(N), warp tile 32x32, m16n8k16.
// ==================================================================
#define BKB 64
#define SSB 72   // smem row stride in halves (144B): LDSM phase conflict-free

template<int SCATTER>
__global__ __launch_bounds__(256)
void gemm_bf16(const __nv_bfloat16* __restrict__ A,
               const __nv_bfloat16* __restrict__ Wt,
               const float* __restrict__ bias,
               void* __restrict__ Cv,
               const int* __restrict__ idx,
               int M, int Kp, int N, int lda, int ldc, int do_relu)
{
    __shared__ __align__(16) __nv_bfloat16 As[2][BM][SSB];
    __shared__ __align__(16) __nv_bfloat16 Ws[2][BN][SSB];

    const int tid  = threadIdx.x;
    const int warp = tid >> 5;
    const int lane = tid & 31;
    const int wm = (warp & 3) * 32;
    const int wn = (warp >> 2) * 32;
    const int n0 = blockIdx.x * BN;   // N-tile fastest => A reuse in L2
    const int m0 = blockIdx.y * BM;

    const int lr = lane >> 2;
    const int lc = lane & 3;

    // ldmatrix addressing roles
    const int aRowOff = lane & 15;           // + wm + mi*16
    const int aColOff = (lane >> 4) << 3;    // + ks (halves)
    const int t8 = lane >> 3, r8 = lane & 7;
    const int bRowOff = ((t8 >> 1) << 3) + r8;  // + wn + p*16
    const int bColOff = (t8 & 1) << 3;          // + ks (halves)

    const uint32_t As32 = (uint32_t)__cvta_generic_to_shared(&As[0][0][0]);
    const uint32_t Ws32 = (uint32_t)__cvta_generic_to_shared(&Ws[0][0][0]);

    // cp.async chunks (16B = 8 halves). A: 4/thread, W: 2/thread.
    int mmA[4], kcA[4];
    const __nv_bfloat16* agp[4];
    bool rowOkA[4];
#pragma unroll
    for (int i = 0; i < 4; i++) {
        int c = tid + i * 256;         // 0..1023
        mmA[i] = c >> 3;               // 8 chunks per 64-half row
        kcA[i] = (c & 7) * 8;
        rowOkA[i] = (m0 + mmA[i]) < M;
        agp[i] = A + (size_t)(rowOkA[i] ? (m0 + mmA[i]) : 0) * lda + kcA[i];
    }
    int nnW[2], kcW[2];
    const __nv_bfloat16* wgp[2];
    bool rowOkW[2];
#pragma unroll
    for (int i = 0; i < 2; i++) {
        int c = tid + i * 256;         // 0..511
        nnW[i] = c >> 3;
        kcW[i] = (c & 7) * 8;
        rowOkW[i] = (n0 + nnW[i]) < N;
        wgp[i] = Wt + (size_t)(rowOkW[i] ? (n0 + nnW[i]) : 0) * Kp + kcW[i];
    }

    float acc[2][4][4];
#pragma unroll
    for (int mi = 0; mi < 2; mi++)
#pragma unroll
        for (int ni = 0; ni < 4; ni++)
#pragma unroll
            for (int r = 0; r < 4; r++) acc[mi][ni][r] = 0.f;

    const int nsteps = (Kp + BKB - 1) / BKB;

    // Prologue
    {
#pragma unroll
        for (int i = 0; i < 4; i++)
            cp_async16(&As[0][mmA[i]][kcA[i]], agp[i],
                       rowOkA[i] && (kcA[i] + 8 <= Kp));
#pragma unroll
        for (int i = 0; i < 2; i++)
            cp_async16(&Ws[0][nnW[i]][kcW[i]], wgp[i],
                       rowOkW[i] && (kcW[i] + 8 <= Kp));
        cp_async_commit();
    }

    for (int s = 0; s < nsteps; s++) {
        const int buf = s & 1;
        if (s + 1 < nsteps) {
            const int k0n = (s + 1) * BKB;
            const int nb = buf ^ 1;
#pragma unroll
            for (int i = 0; i < 4; i++)
                cp_async16(&As[nb][mmA[i]][kcA[i]], agp[i] + k0n,
                           rowOkA[i] && (k0n + kcA[i] + 8 <= Kp));
#pragma unroll
            for (int i = 0; i < 2; i++)
                cp_async16(&Ws[nb][nnW[i]][kcW[i]], wgp[i] + k0n,
                           rowOkW[i] && (k0n + kcW[i] + 8 <= Kp));
            cp_async_commit();
            cp_async_wait<1>();
        } else {
            cp_async_wait<0>();
        }
        __syncthreads();

        const uint32_t aBufBase = As32 + (uint32_t)buf * (BM * SSB * 2);
        const uint32_t wBufBase = Ws32 + (uint32_t)buf * (BN * SSB * 2);

#pragma unroll
        for (int ks = 0; ks < BKB; ks += 16) {
            uint32_t a[2][4], b[4][2];
#pragma unroll
            for (int mi = 0; mi < 2; mi++) {
                uint32_t addr = aBufBase +
                    (uint32_t)(((wm + mi * 16 + aRowOff) * SSB + ks + aColOff) * 2);
                ldsm_x4(a[mi][0], a[mi][1], a[mi][2], a[mi][3], addr);
            }
#pragma unroll
            for (int p = 0; p < 2; p++) {
                uint32_t addr = wBufBase +
                    (uint32_t)(((wn + p * 16 + bRowOff) * SSB + ks + bColOff) * 2);
                ldsm_x4(b[2 * p][0], b[2 * p][1], b[2 * p + 1][0], b[2 * p + 1][1], addr);
            }
#pragma unroll
            for (int mi = 0; mi < 2; mi++)
#pragma unroll
                for (int ni = 0; ni < 4; ni++) {
                    asm volatile(
                        "mma.sync.aligned.m16n8k16.row.col.f32.bf16.bf16.f32 "
                        "{%0,%1,%2,%3}, {%4,%5,%6,%7}, {%8,%9}, {%0,%1,%2,%3};\n"
                        : "+f"(acc[mi][ni][0]), "+f"(acc[mi][ni][1]),
                          "+f"(acc[mi][ni][2]), "+f"(acc[mi][ni][3])
                        : "r"(a[mi][0]), "r"(a[mi][1]), "r"(a[mi][2]), "r"(a[mi][3]),
                          "r"(b[ni][0]), "r"(b[ni][1]));
                }
        }
        __syncthreads();
    }

    // Epilogue
#pragma unroll
    for (int mi = 0; mi < 2; mi++) {
#pragma unroll
        for (int half = 0; half < 2; half++) {
            int row = m0 + wm + mi * 16 + lr + half * 8;
            if (row >= M) continue;
            long long obase;
            if (SCATTER) obase = (long long)idx[row] * ldc;
            else         obase = (long long)row * ldc;
#pragma unroll
            for (int ni = 0; ni < 4; ni++) {
                int col = n0 + wn + ni * 8 + lc * 2;
                if (col >= N) continue;  // N even => col,col+1 together
                float v0 = acc[mi][ni][half * 2 + 0] + bias[col];
                float v1 = acc[mi][ni][half * 2 + 1] + bias[col + 1];
                if (do_relu) { v0 = fmaxf(v0, 0.f); v1 = fmaxf(v1, 0.f); }
                if (SCATTER) {
                    float* C = (float*)Cv;
                    atomicAdd(&C[obase + col], v0);
                    atomicAdd(&C[obase + col + 1], v1);
                } else {
                    __nv_bfloat162 pk = __floats2bfloat162_rn(v0, v1);
                    *reinterpret_cast<__nv_bfloat162*>(
                        (__nv_bfloat16*)Cv + obase + col) = pk;
                }
            }
        }
    }
}

// ==================================================================
// tf32 GEMM (node MLP) — unchanged from Round 6.
// ==================================================================
#define BKT 32
#define SST 36   // floats per smem row (144B)

template<int CVTA>
__global__ __launch_bounds__(256)
void gemm_tf32(const float* __restrict__ A,
               const float* __restrict__ Wt,     // [N, K]
               const float* __restrict__ bias,
               float* __restrict__ C,
               const int* __restrict__ idx,
               int M, int K, int N, int do_relu, int round_out)
{
    __shared__ __align__(16) float As[2][BM][SST];
    __shared__ __align__(16) float Ws[2][BN][SST];

    const int tid  = threadIdx.x;
    const int warp = tid >> 5;
    const int lane = tid & 31;
    const int wm = (warp & 3) * 32;
    const int wn = (warp >> 2) * 32;
    const int n0 = blockIdx.x * BN;
    const int m0 = blockIdx.y * BM;

    const int lr = lane >> 2;
    const int lc = lane & 3;

    const int t8 = lane >> 3;
    const int r8 = lane & 7;
    const int aRowOff = ((t8 & 1) << 3) + r8;
    const int aColOff = (t8 >> 1) << 2;
    const int bRowOff = ((t8 >> 1) << 3) + r8;
    const int bColOff = (t8 & 1) << 2;

    const uint32_t As32 = (uint32_t)__cvta_generic_to_shared(&As[0][0][0]);
    const uint32_t Ws32 = (uint32_t)__cvta_generic_to_shared(&Ws[0][0][0]);

    int mmA[4], kcA[4];
    const float* agp[4];
    bool rowOkA[4];
#pragma unroll
    for (int i = 0; i < 4; i++) {
        int c = tid + i * 256;
        mmA[i] = c >> 3;
        kcA[i] = (c & 7) * 4;
        rowOkA[i] = (m0 + mmA[i]) < M;
        agp[i] = A + (size_t)(rowOkA[i] ? (m0 + mmA[i]) : 0) * K + kcA[i];
    }
    int nnW[2], kcW[2];
    const float* wgp[2];
    bool rowOkW[2];
#pragma unroll
    for (int i = 0; i < 2; i++) {
        int c = tid + i * 256;
        nnW[i] = c >> 3;
        kcW[i] = (c & 7) * 4;
        rowOkW[i] = (n0 + nnW[i]) < N;
        wgp[i] = Wt + (size_t)(rowOkW[i] ? (n0 + nnW[i]) : 0) * K + kcW[i];
    }

    float acc[2][4][4];
#pragma unroll
    for (int mi = 0; mi < 2; mi++)
#pragma unroll
        for (int ni = 0; ni < 4; ni++)
#pragma unroll
            for (int r = 0; r < 4; r++) acc[mi][ni][r] = 0.f;

    const int nsteps = (K + BKT - 1) / BKT;

    {
#pragma unroll
        for (int i = 0; i < 4; i++)
            cp_async16(&As[0][mmA[i]][kcA[i]], agp[i], rowOkA[i] && (kcA[i] < K));
#pragma unroll
        for (int i = 0; i < 2; i++)
            cp_async16(&Ws[0][nnW[i]][kcW[i]], wgp[i], rowOkW[i] && (kcW[i] < K));
        cp_async_commit();
    }

    for (int s = 0; s < nsteps; s++) {
        const int buf = s & 1;
        if (s + 1 < nsteps) {
            const int k0n = (s + 1) * BKT;
            const int nb = buf ^ 1;
#pragma unroll
            for (int i = 0; i < 4; i++)
                cp_async16(&As[nb][mmA[i]][kcA[i]], agp[i] + k0n,
                           rowOkA[i] && (k0n + kcA[i] < K));
#pragma unroll
            for (int i = 0; i < 2; i++)
                cp_async16(&Ws[nb][nnW[i]][kcW[i]], wgp[i] + k0n,
                           rowOkW[i] && (k0n + kcW[i] < K));
            cp_async_commit();
            cp_async_wait<1>();
        } else {
            cp_async_wait<0>();
        }
        __syncthreads();

        const uint32_t aBufBase = As32 + (uint32_t)buf * (BM * SST * 4);
        const uint32_t wBufBase = Ws32 + (uint32_t)buf * (BN * SST * 4);

#pragma unroll
        for (int ks = 0; ks < BKT; ks += 8) {
            uint32_t a[2][4], b[4][2];
#pragma unroll
            for (int mi = 0; mi < 2; mi++) {
                uint32_t addr = aBufBase +
                    (uint32_t)(((wm + mi * 16 + aRowOff) * SST + ks + aColOff) * 4);
                ldsm_x4(a[mi][0], a[mi][1], a[mi][2], a[mi][3], addr);
                if (CVTA) {
#pragma unroll
                    for (int q = 0; q < 4; q++)
                        a[mi][q] = f2tf32(__uint_as_float(a[mi][q]));
                }
            }
#pragma unroll
            for (int p = 0; p < 2; p++) {
                uint32_t addr = wBufBase +
                    (uint32_t)(((wn + p * 16 + bRowOff) * SST + ks + bColOff) * 4);
                ldsm_x4(b[2 * p][0], b[2 * p][1], b[2 * p + 1][0], b[2 * p + 1][1], addr);
            }
#pragma unroll
            for (int mi = 0; mi < 2; mi++)
#pragma unroll
                for (int ni = 0; ni < 4; ni++) {
                    asm volatile(
                        "mma.sync.aligned.m16n8k8.row.col.f32.tf32.tf32.f32 "
                        "{%0,%1,%2,%3}, {%4,%5,%6,%7}, {%8,%9}, {%0,%1,%2,%3};\n"
                        : "+f"(acc[mi][ni][0]), "+f"(acc[mi][ni][1]),
                          "+f"(acc[mi][ni][2]), "+f"(acc[mi][ni][3])
                        : "r"(a[mi][0]), "r"(a[mi][1]), "r"(a[mi][2]), "r"(a[mi][3]),
                          "r"(b[ni][0]), "r"(b[ni][1]));
                }
        }
        __syncthreads();
    }

#pragma unroll
    for (int mi = 0; mi < 2; mi++) {
#pragma unroll
        for (int half = 0; half < 2; half++) {
            int row = m0 + wm + mi * 16 + lr + half * 8;
            if (row >= M) continue;
            long long obase;
            if (idx) obase = (long long)idx[row] * N;
            else     obase = (long long)row * N;
#pragma unroll
            for (int ni = 0; ni < 4; ni++) {
                int col = n0 + wn + ni * 8 + lc * 2;
#pragma unroll
                for (int q = 0; q < 2; q++) {
                    if (col + q >= N) continue;
                    float v = acc[mi][ni][half * 2 + q] + bias[col + q];
                    if (do_relu) v = fmaxf(v, 0.f);
                    if (round_out) v = round_tf32(v);
                    if (idx) atomicAdd(&C[obase + col + q], v);
                    else     C[obase + col + q] = v;
                }
            }
        }
    }
}

// ------------------------------------------------------------------
// Pool count + final linear
// ------------------------------------------------------------------
__global__ void pool_cnt_kernel(const int* __restrict__ batch,
                                float* __restrict__ gcnt, int Nn)
{
    int n = blockIdx.x * blockDim.x + threadIdx.x;
    if (n >= Nn) return;
    atomicAdd(&gcnt[batch[n]], 1.0f);
}

__global__ void final_kernel(const float* __restrict__ gsum,
                             const float* __restrict__ gcnt,
                             const float* __restrict__ lw,
                             const float* __restrict__ lb,
                             float* __restrict__ out)
{
    int t = threadIdx.x;
    if (t >= NGRAPH * NPRED) return;
    int g = t / NPRED;
    int p = t % NPRED;
    float inv = 1.0f / fmaxf(gcnt[g], 1.0f);
    float s = 0.f;
    for (int k = 0; k < HID; k++)
        s = fmaf(gsum[g * HID + k] * inv, lw[k * NPRED + p], s);
    out[t] = s + lb[p];
}

// ------------------------------------------------------------------
// Launch
// ------------------------------------------------------------------
static inline int cdiv(int a, int b) { return (a + b - 1) / b; }

extern "C" void kernel_launch(void* const* d_in, const int* in_sizes, int n_in,
                              void* d_out, int out_size)
{
    const float* x   = (const float*)d_in[0];
    const int*   ei  = (const int*)d_in[1];
    const float* ea  = (const float*)d_in[2];
    const int*   bat = (const int*)d_in[3];
    const float* mw1 = (const float*)d_in[4];
    const float* mb1 = (const float*)d_in[5];
    const float* mw2 = (const float*)d_in[6];
    const float* mb2 = (const float*)d_in[7];
    const float* mw3 = (const float*)d_in[8];
    const float* mb3 = (const float*)d_in[9];
    const float* mw4 = (const float*)d_in[10];
    const float* mb4 = (const float*)d_in[11];
    const float* nw1 = (const float*)d_in[12];
    const float* nb1 = (const float*)d_in[13];
    const float* nw2 = (const float*)d_in[14];
    const float* nb2 = (const float*)d_in[15];
    const float* nw3 = (const float*)d_in[16];
    const float* nb3 = (const float*)d_in[17];
    const float* nw4 = (const float*)d_in[18];
    const float* nb4 = (const float*)d_in[19];
    const float* lw  = (const float*)d_in[20];
    const float* lb  = (const float*)d_in[21];
    float* out = (float*)d_out;

    const int E  = in_sizes[1] / 2;
    const int Nn = in_sizes[0] / N_NF;
    const int* src = ei;
    const int* dst = ei + E;

    __nv_bfloat16 *featb, *bbuf1, *bbuf2, *wbf;
    float *aggr, *n1, *n2, *gsum, *gcnt, *wnd;
    cudaGetSymbolAddress((void**)&featb, g_featb);
    cudaGetSymbolAddress((void**)&bbuf1, g_bbuf1);
    cudaGetSymbolAddress((void**)&bbuf2, g_bbuf2);
    cudaGetSymbolAddress((void**)&aggr,  g_aggr);
    cudaGetSymbolAddress((void**)&n1,    g_n1);
    cudaGetSymbolAddress((void**)&n2,    g_n2);
    cudaGetSymbolAddress((void**)&gsum,  g_gsum);
    cudaGetSymbolAddress((void**)&gcnt,  g_gcnt);
    cudaGetSymbolAddress((void**)&wbf,   g_wbf);
    cudaGetSymbolAddress((void**)&wnd,   g_wnd);

    // edge bf16 weights [N][Kp]
    __nv_bfloat16* wb_mw1 = wbf;                          // [300][48]
    __nv_bfloat16* wb_mw2 = wb_mw1 + 300 * FEATP;         // [300][304]
    __nv_bfloat16* wb_mw3 = wb_mw2 + 300 * HIDP;          // [300][304]
    __nv_bfloat16* wb_mw4 = wb_mw3 + 300 * HIDP;          // [128][304]
    // node fp32 weights [N][K]
    float* wn_nw1 = wnd;                                  // [300][128]
    float* wn_nw2 = wn_nw1 + 300 * 128;                   // [300][300]
    float* wn_nw3 = wn_nw2 + 300 * 300;
    float* wn_nw4 = wn_nw3 + 300 * 300;

    cudaMemsetAsync(aggr, 0, (size_t)N_NODES * MSGD * sizeof(float));
    cudaMemsetAsync(gsum, 0, (size_t)NGRAPH * HID * sizeof(float));
    cudaMemsetAsync(gcnt, 0, (size_t)NGRAPH * sizeof(float));

    // 0. Weight prep
    prep_wbf_kernel<<<cdiv(300 * FEATP, 256), 256>>>(mw1, wb_mw1, FEAT, 300, FEATP);
    prep_wbf_kernel<<<cdiv(300 * HIDP, 256), 256>>>(mw2, wb_mw2, HID, 300, HIDP);
    prep_wbf_kernel<<<cdiv(300 * HIDP, 256), 256>>>(mw3, wb_mw3, HID, 300, HIDP);
    prep_wbf_kernel<<<cdiv(128 * HIDP, 256), 256>>>(mw4, wb_mw4, HID, 128, HIDP);
    round_wT_kernel<<<cdiv(128 * 300, 256), 256>>>(nw1, wn_nw1, 128, 300);
    round_wT_kernel<<<cdiv(300 * 300, 256), 256>>>(nw2, wn_nw2, 300, 300);
    round_wT_kernel<<<cdiv(300 * 300, 256), 256>>>(nw3, wn_nw3, 300, 300);
    round_wT_kernel<<<cdiv(300 * 300, 256), 256>>>(nw4, wn_nw4, 300, 300);

    // 1. Gather edge features -> bf16 [E][48]
    {
        long long total = (long long)E * FEAT;
        gather_feat_kernel<<<(int)((total + 255) / 256), 256>>>(x, src, dst, ea, featb, E);
    }

    // 2. Edge MLP (bf16): 40->300->300->300->128; layer 4 scatters into aggr
    {
        dim3 grid(cdiv(HID, BN), cdiv(E, BM));
        gemm_bf16<0><<<grid, 256>>>(featb, wb_mw1, mb1, bbuf1, nullptr,
                                    E, FEATP, HID, FEATP, HIDP, 1);
        gemm_bf16<0><<<grid, 256>>>(bbuf1, wb_mw2, mb2, bbuf2, nullptr,
                                    E, HIDP, HID, HIDP, HIDP, 1);
        gemm_bf16<0><<<grid, 256>>>(bbuf2, wb_mw3, mb3, bbuf1, nullptr,
                                    E, HIDP, HID, HIDP, HIDP, 1);
        dim3 grid4(cdiv(MSGD, BN), cdiv(E, BM));
        gemm_bf16<1><<<grid4, 256>>>(bbuf1, wb_mw4, mb4, aggr, dst,
                                     E, HIDP, MSGD, HIDP, MSGD, 0);
    }

    // 3. Node MLP (tf32): 128->300->300->300->300; layer 4 scatters into gsum
    {
        dim3 grid(cdiv(HID, BN), cdiv(Nn, BM));
        gemm_tf32<1><<<grid, 256>>>(aggr, wn_nw1, nb1, n1, nullptr, Nn, MSGD, HID, 1, 1);
        gemm_tf32<0><<<grid, 256>>>(n1,   wn_nw2, nb2, n2, nullptr, Nn, HID,  HID, 1, 1);
        gemm_tf32<0><<<grid, 256>>>(n2,   wn_nw3, nb3, n1, nullptr, Nn, HID,  HID, 1, 1);
        gemm_tf32<0><<<grid, 256>>>(n1,   wn_nw4, nb4, gsum, bat,   Nn, HID,  HID, 0, 0);
    }

    // 4. Counts + final linear
    pool_cnt_kernel<<<cdiv(Nn, 256), 256>>>(bat, gcnt, Nn);
    final_kernel<<<1, 512>>>(gsum, gcnt, lw, lb, out);
}